// round 12
// baseline (speedup 1.0000x reference)
#include <cuda_runtime.h>
#include <cuda_bf16.h>
#include <cuda_fp16.h>
#include <cstdint>

#define HH 128
#define WW 128
#define CH 64
#define BATCH 4
#define EPS 1e-5f

// ---------------- scratch (no mallocs allowed) ----------------
__device__ __align__(16) float g_xnhwc[BATCH*HH*WW*CH];
__device__ __align__(16) float g_y1   [BATCH*HH*WW*CH];
__device__ __align__(16) float g_off  [BATCH*HH*WW*18];   // layout [bh][18][128]
__device__ __align__(1024) __nv_bfloat16 g_wtb1[9*2*64*64];  // fp16 bits: hi/mid per tap
__device__ __align__(1024) __nv_bfloat16 g_wtb2[9*2*64*64];
__device__ __align__(1024) __nv_bfloat16 g_wob1[9*2*32*64];  // bf16 hi/mid (offconv)
__device__ __align__(1024) __nv_bfloat16 g_wob2[9*2*32*64];
__device__ __align__(16) float g_bn[256];

// ---------------- helpers ----------------
static __device__ __forceinline__ uint32_t smem_to_u32(const void* p){
    uint32_t a;
    asm("{ .reg .u64 t; cvta.to.shared.u64 t, %1; cvt.u32.u64 %0, t; }" : "=r"(a) : "l"(p));
    return a;
}
#define SWZ128(o) ((o) ^ (((o) >> 3) & 0x70))

#define LDSM4(r, a) \
    asm volatile("ldmatrix.sync.aligned.m8n8.x4.shared.b16 {%0,%1,%2,%3}, [%4];" \
        : "=r"((r)[0]), "=r"((r)[1]), "=r"((r)[2]), "=r"((r)[3]) : "r"(a))

static __device__ __forceinline__ void mma_bf16(float* d, const uint32_t* a, uint32_t b0, uint32_t b1){
    asm volatile("mma.sync.aligned.m16n8k16.row.col.f32.bf16.bf16.f32 "
        "{%0,%1,%2,%3},{%4,%5,%6,%7},{%8,%9},{%0,%1,%2,%3};"
        : "+f"(d[0]), "+f"(d[1]), "+f"(d[2]), "+f"(d[3])
        : "r"(a[0]), "r"(a[1]), "r"(a[2]), "r"(a[3]), "r"(b0), "r"(b1));
}
static __device__ __forceinline__ void mma_f16(float* d, const uint32_t* a, uint32_t b0, uint32_t b1){
    asm volatile("mma.sync.aligned.m16n8k16.row.col.f32.f16.f16.f32 "
        "{%0,%1,%2,%3},{%4,%5,%6,%7},{%8,%9},{%0,%1,%2,%3};"
        : "+f"(d[0]), "+f"(d[1]), "+f"(d[2]), "+f"(d[3])
        : "r"(a[0]), "r"(a[1]), "r"(a[2]), "r"(a[3]), "r"(b0), "r"(b1));
}

#define CP_ASYNC16(dst, src) \
    asm volatile("cp.async.cg.shared.global [%0], [%1], 16;" :: "r"(dst), "l"(src) : "memory")
#define CP_COMMIT() asm volatile("cp.async.commit_group;" ::: "memory")
#define CP_WAIT0()  asm volatile("cp.async.wait_group 0;" ::: "memory")

// ---------------- prep ----------------
__global__ void k_prep(const float* __restrict__ w1, const float* __restrict__ w2,
                       const float* __restrict__ woff1, const float* __restrict__ woff2,
                       const float* g1, const float* be1, const float* m1, const float* v1,
                       const float* g2, const float* be2, const float* m2, const float* v2)
{
    int i = blockIdx.x*blockDim.x + threadIdx.x;
    if(i < 73728){
        // main conv weights -> fp16 hi/mid per-tap SW128 tiles
        int L   = i / 36864;
        int rem = i % 36864;
        int k = rem >> 12;
        int o = (rem >> 6) & 63;
        int c = rem & 63;
        const float* w = L ? w2 : w1;
        float val = w[(o*64 + c)*9 + k];
        __half hb = __float2half_rn(val);
        float hf = __half2float(hb);
        __half mb = __float2half_rn(val - hf);
        char* dst = (char*)(L ? g_wtb2 : g_wtb1);
        int sw = SWZ128(o*128 + c*2);
        *(__half*)(dst + k*16384 +        sw) = hb;
        *(__half*)(dst + k*16384 + 8192 + sw) = mb;
    } else if(i < 110592){
        // offset conv weights (bf16 hi/mid)
        int j   = i - 73728;
        int L   = j / 18432;
        int rem = j % 18432;
        int k = rem >> 11;
        int o = (rem >> 6) & 31;
        int c = rem & 63;
        const float* w = L ? woff2 : woff1;
        float val = (o < 18) ? w[(o*64 + c)*9 + k] : 0.f;
        __nv_bfloat16 hb = __float2bfloat16(val);
        float hf = __bfloat162float(hb);
        __nv_bfloat16 mb = __float2bfloat16(val - hf);
        char* dst = (char*)(L ? g_wob2 : g_wob1);
        int sw = SWZ128(o*128 + c*2);
        *(__nv_bfloat16*)(dst + k*8192 +        sw) = hb;
        *(__nv_bfloat16*)(dst + k*8192 + 4096 + sw) = mb;
    }
    if(blockIdx.x == 0 && threadIdx.x < 64){
        int t = threadIdx.x;
        float i1 = g1[t] * rsqrtf(v1[t] + EPS);
        g_bn[t]      = i1;
        g_bn[64+t]   = be1[t] - m1[t]*i1;
        float i2 = g2[t] * rsqrtf(v2[t] + EPS);
        g_bn[128+t]  = i2;
        g_bn[192+t]  = be2[t] - m2[t]*i2;
    }
}

// ---------------- NCHW -> NHWC transpose ----------------
__global__ void k_nchw2nhwc(const float* __restrict__ x, float* __restrict__ xn){
    __shared__ float tile[64*129];
    int b = blockIdx.x >> 7;
    int h = blockIdx.x & 127;
    const float* src = x + (b*CH*HH)*WW + h*WW;
    for(int i = threadIdx.x; i < CH*WW; i += blockDim.x){
        int c = i >> 7, w = i & 127;
        tile[c*129 + w] = src[c*HH*WW + w];
    }
    __syncthreads();
    float* dst = xn + ((b*HH + h)*WW)*CH;
    for(int i = threadIdx.x; i < CH*WW; i += blockDim.x){
        int w = i >> 6, c = i & 63;
        dst[w*CH + c] = tile[c*129 + w];
    }
}

// ---------------- offset conv v2 (bf16 3-term, unchanged) ----------------
#define OT2_A_HI  0
#define OT2_A_MID 16640
#define OT2_B     33280
#define OT2_SMEM  49664

__global__ void __launch_bounds__(256,3) k_offt(
    const float* __restrict__ xn, const __nv_bfloat16* __restrict__ wob,
    const float* __restrict__ boff, float* __restrict__ off)
{
    extern __shared__ char smc[];
    const uint32_t smem_base = smem_to_u32(smc);

    const int b = blockIdx.x >> 7;
    const int h = blockIdx.x & 127;
    const int tid = threadIdx.x;
    const int wid = tid >> 5;
    const int lid = tid & 31;
    const int m0 = wid * 16;

    const uint32_t aKh = (lid >> 4) * 16;
    const int aR = m0 + (lid & 15);
    uint32_t bRow[2], bXor[2];
    #pragma unroll
    for(int ni = 0; ni < 2; ni++){
        int r = ni*16 + (lid & 7) + ((lid >> 4) << 3);
        bRow[ni] = r*128;
        bXor[ni] = (r & 7) << 4;
    }
    const uint32_t bKh = ((lid >> 3) & 1) * 16;

    float acc[3][4];
    #pragma unroll
    for(int n8 = 0; n8 < 3; n8++)
        #pragma unroll
        for(int j = 0; j < 4; j++) acc[n8][j] = 0.f;

    {
        const char* bs = (const char*)wob;
        #pragma unroll
        for(int j = 0; j < 2; j++)
            CP_ASYNC16(smem_base + OT2_B + tid*16 + j*4096, bs + tid*16 + j*4096);
        CP_COMMIT();
    }

    #pragma unroll 1
    for(int ky = 0; ky < 3; ky++){
        __syncthreads();
        const int hh = h + ky - 1;
        const bool hv = (hh >= 0) && (hh < HH);
        const float* rowp = xn + (size_t)(b*HH + hh)*WW*CH;
        #pragma unroll 1
        for(int idx = tid; idx < 2080; idx += 256){
            int rho = idx >> 4, q = idx & 15;
            int px = rho - 1;
            float4 v = make_float4(0.f,0.f,0.f,0.f);
            if(hv && px >= 0 && px < WW)
                v = __ldg((const float4*)(rowp + px*CH) + q);
            __nv_bfloat162 h0 = __float22bfloat162_rn(make_float2(v.x, v.y));
            __nv_bfloat162 h1 = __float22bfloat162_rn(make_float2(v.z, v.w));
            float2 f0 = __bfloat1622float2(h0);
            float2 f1 = __bfloat1622float2(h1);
            __nv_bfloat162 m0b = __float22bfloat162_rn(make_float2(v.x - f0.x, v.y - f0.y));
            __nv_bfloat162 m1b = __float22bfloat162_rn(make_float2(v.z - f1.x, v.w - f1.y));
            int sw = SWZ128(rho*128 + q*8);
            uint2 uh, um;
            uh.x = *(uint32_t*)&h0;  uh.y = *(uint32_t*)&h1;
            um.x = *(uint32_t*)&m0b; um.y = *(uint32_t*)&m1b;
            *(uint2*)(smc + OT2_A_HI  + sw) = uh;
            *(uint2*)(smc + OT2_A_MID + sw) = um;
        }

        #pragma unroll 1
        for(int kx = 0; kx < 3; kx++){
            int k = ky*3 + kx;
            CP_WAIT0();
            __syncthreads();
            if(k < 8){
                const char* bs = (const char*)wob + (k+1)*8192;
                uint32_t bd = smem_base + OT2_B + ((k+1)&1)*8192;
                #pragma unroll
                for(int j = 0; j < 2; j++)
                    CP_ASYNC16(bd + tid*16 + j*4096, bs + tid*16 + j*4096);
                CP_COMMIT();
            }
            const uint32_t slotB = smem_base + OT2_B + (k&1)*8192;
            const int rho = aR + 1 + kx - 1;
            const uint32_t aAddrBase = smem_base + OT2_A_HI + rho*128;
            const uint32_t aXor = (rho & 7) << 4;

            #pragma unroll
            for(int ks = 0; ks < 4; ks++){
                uint32_t ahi[4], ami[4], bhi[2][4], bmi[2][4];
                uint32_t ad = aAddrBase + ((ks*32 + aKh) ^ aXor);
                LDSM4(ahi, ad);
                LDSM4(ami, ad + (OT2_A_MID - OT2_A_HI));
                uint32_t cb = ks*32 + bKh;
                #pragma unroll
                for(int ni = 0; ni < 2; ni++){
                    uint32_t bd = slotB + bRow[ni] + (cb ^ bXor[ni]);
                    LDSM4(bhi[ni], bd);
                    LDSM4(bmi[ni], bd + 4096);
                }
                #pragma unroll
                for(int n8 = 0; n8 < 3; n8++){
                    uint32_t bh0 = bhi[n8>>1][(n8&1)*2], bh1 = bhi[n8>>1][(n8&1)*2+1];
                    uint32_t bm0 = bmi[n8>>1][(n8&1)*2], bm1 = bmi[n8>>1][(n8&1)*2+1];
                    mma_bf16(acc[n8], ahi, bh0, bh1);
                    mma_bf16(acc[n8], ahi, bm0, bm1);
                    mma_bf16(acc[n8], ami, bh0, bh1);
                }
            }
        }
    }

    const int r0 = m0 + (lid >> 2);
    const int r1 = r0 + 8;
    float* base = off + (size_t)(b*HH + h)*2304;
    #pragma unroll
    for(int n8 = 0; n8 < 3; n8++){
        int c0 = n8*8 + (lid & 3)*2;
        if(c0 < 18){
            float b0 = __ldg(boff + c0);
            float b1v = __ldg(boff + c0 + 1);
            base[c0*128 + r0]     = acc[n8][0] + b0;
            base[(c0+1)*128 + r0] = acc[n8][1] + b1v;
            base[c0*128 + r1]     = acc[n8][2] + b0;
            base[(c0+1)*128 + r1] = acc[n8][3] + b1v;
        }
    }
}

// ---------------- main DCN v10: fp16 2-pass, 3 CTAs/SM, quantized table, B single ----------------
#define TBQ_OFF   0          /* uint2 wq[1152] = 9216 (w00..w11 u16 fixed-point) */
#define TBI_OFF   9216       /* uint  itab[1152] = 4608 */
#define A_OFF     13824      /* 2 x 16384 fp16 A (dbl buf) */
#define B_OFF     46592      /* hi 8192 + mid 8192 (single, cp.async) */
#define DCN_SMEM  62976

template<bool NCHW_OUT>
__global__ void __launch_bounds__(256,3) k_dcn(
    const float* __restrict__ xn, const float* __restrict__ off,
    const __nv_bfloat16* __restrict__ wtb, const float* __restrict__ bn,
    float* __restrict__ out)
{
    extern __shared__ char smc[];
    const uint32_t smem_base = smem_to_u32(smc);

    const int b = blockIdx.x >> 7;
    const int h = blockIdx.x & 127;
    const int tid = threadIdx.x;
    const int wid = tid >> 5;
    const int lid = tid & 31;
    const float fh = (float)h;

    // prefetch B(0): 16KB via cp.async (hidden behind table build + prologue gather)
    {
        const char* bs = (const char*)wtb;
        #pragma unroll
        for(int j = 0; j < 4; j++)
            CP_ASYNC16(smem_base + B_OFF + tid*16 + j*4096, bs + tid*16 + j*4096);
        CP_COMMIT();
    }

    // ---------- build quantized gather table (12B/entry, premasked fixed-point weights) ----------
    {
        uint2*    wq = (uint2*)(smc + TBQ_OFF);
        uint32_t* it = (uint32_t*)(smc + TBI_OFF);
        const float* offb2 = off + (size_t)(b*HH + h)*2304;
        #pragma unroll 1
        for(int e = tid; e < 1152; e += 256){
            int k  = e >> 7;
            int px = e & 127;
            float dy = __ldg(offb2 + (2*k)*128 + px);
            float dx = __ldg(offb2 + (2*k+1)*128 + px);
            float py  = fh + (float)(k/3 - 1) + dy;
            float pxx = (float)(px + k%3 - 1) + dx;
            float y0f = floorf(py), x0f = floorf(pxx);
            float wy1 = py - y0f,  wx1 = pxx - x0f;
            float wy0 = 1.f - wy1, wx0 = 1.f - wx1;
            bool vy0 = (y0f >= 0.f)  && (y0f <= 127.f);
            bool vy1 = (y0f >= -1.f) && (y0f <= 126.f);
            bool vx0 = (x0f >= 0.f)  && (x0f <= 127.f);
            bool vx1 = (x0f >= -1.f) && (x0f <= 126.f);
            float ay0 = vy0 ? wy0 : 0.f;
            float ay1 = vy1 ? wy1 : 0.f;
            float ax0 = vx0 ? wx0 : 0.f;
            float ax1 = vx1 ? wx1 : 0.f;
            uint32_t yi0 = (uint32_t)(int)fminf(fmaxf(y0f,      0.f),127.f);
            uint32_t yi1 = (uint32_t)(int)fminf(fmaxf(y0f + 1.f,0.f),127.f);
            uint32_t xi0 = (uint32_t)(int)fminf(fmaxf(x0f,      0.f),127.f);
            uint32_t xi1 = (uint32_t)(int)fminf(fmaxf(x0f + 1.f,0.f),127.f);
            uint32_t q00 = (uint32_t)(ay0*ax0*65535.f + 0.5f);
            uint32_t q01 = (uint32_t)(ay0*ax1*65535.f + 0.5f);
            uint32_t q10 = (uint32_t)(ay1*ax0*65535.f + 0.5f);
            uint32_t q11 = (uint32_t)(ay1*ax1*65535.f + 0.5f);
            wq[e] = make_uint2(q00 | (q01 << 16), q10 | (q11 << 16));
            it[e] = yi0 | (yi1 << 7) | (xi0 << 14) | (xi1 << 21);
        }
    }

    const char* xq = (const char*)(xn + (size_t)b*HH*WW*CH) + (tid & 15)*16;
    const int q  = tid & 15;
    const int pg = tid >> 4;

    __syncthreads();  // table visible

    const uint2*    wq  = (const uint2*)(smc + TBQ_OFF);
    const uint32_t* itb = (const uint32_t*)(smc + TBI_OFF);

    // gather one pixel of tap k into A buffer `buf` (fp16 single term)
    auto gather_px = [&](int k, int px, int buf){
        int e = k*128 + px;
        uint2 wp = wq[e];
        uint32_t ii = itb[e];
        const float s = 1.f/65535.f;
        float w00 = (float)(wp.x & 0xffffu) * s;
        float w01 = (float)(wp.x >> 16)     * s;
        float w10 = (float)(wp.y & 0xffffu) * s;
        float w11 = (float)(wp.y >> 16)     * s;
        uint32_t ry0 = (ii & 0x7fu) << 15;
        uint32_t ry1 = ((ii >> 7) & 0x7fu) << 15;
        uint32_t rx0 = ((ii >> 14) & 0x7fu) << 8;
        uint32_t rx1 = ((ii >> 21) & 0x7fu) << 8;
        float4 a  = __ldg((const float4*)(xq + ry0 + rx0));
        float4 b2 = __ldg((const float4*)(xq + ry0 + rx1));
        float4 c  = __ldg((const float4*)(xq + ry1 + rx0));
        float4 d  = __ldg((const float4*)(xq + ry1 + rx1));
        float4 r;
        r.x = w00*a.x + w01*b2.x + w10*c.x + w11*d.x;
        r.y = w00*a.y + w01*b2.y + w10*c.y + w11*d.y;
        r.z = w00*a.z + w01*b2.z + w10*c.z + w11*d.z;
        r.w = w00*a.w + w01*b2.w + w10*c.w + w11*d.w;
        __half2 h0 = __float22half2_rn(make_float2(r.x, r.y));
        __half2 h1 = __float22half2_rn(make_float2(r.z, r.w));
        int sw = SWZ128(px*128 + q*8);
        uint2 uh;
        uh.x = *(uint32_t*)&h0;  uh.y = *(uint32_t*)&h1;
        *(uint2*)(smc + A_OFF + buf*16384 + sw) = uh;
    };

    // prologue: gather A(0) into buf 0
    #pragma unroll 2
    for(int i = 0; i < 8; i++) gather_px(0, pg*8 + i, 0);

    // mma mapping: warp (4 x 2) grid of 32x32 tiles
    const int m0 = (wid >> 1) * 32;
    const int n0 = (wid & 1) * 32;

    uint32_t aRow[2], aXor[2];
    #pragma unroll
    for(int mi = 0; mi < 2; mi++){
        int r = m0 + mi*16 + (lid & 15);
        aRow[mi] = r*128;
        aXor[mi] = (r & 7) << 4;
    }
    const uint32_t aKh = (lid >> 4) * 16;
    uint32_t bRow[2], bXor[2];
    #pragma unroll
    for(int ni = 0; ni < 2; ni++){
        int r = n0 + ni*16 + (lid & 7) + ((lid >> 4) << 3);
        bRow[ni] = r*128;
        bXor[ni] = (r & 7) << 4;
    }
    const uint32_t bKh = ((lid >> 3) & 1) * 16;

    float acc[2][4][4];
    #pragma unroll
    for(int mi = 0; mi < 2; mi++)
        #pragma unroll
        for(int ni = 0; ni < 4; ni++)
            #pragma unroll
            for(int j = 0; j < 4; j++) acc[mi][ni][j] = 0.f;

    int cur = 0;
    #pragma unroll 1
    for(int k = 0; k < 9; k++){
        __syncthreads();     // mma(k-1) done: B slot free, A(k) writes visible
        if(k > 0){
            const char* bs = (const char*)wtb + k*16384;
            #pragma unroll
            for(int j = 0; j < 4; j++)
                CP_ASYNC16(smem_base + B_OFF + tid*16 + j*4096, bs + tid*16 + j*4096);
            CP_COMMIT();
        }
        CP_WAIT0();          // B(k) landed (k=0: prologue issue, fully hidden)
        __syncthreads();     // B(k) visible to all

        const uint32_t aB    = smem_base + A_OFF + cur*16384;
        const uint32_t slotB = smem_base + B_OFF;

        #pragma unroll
        for(int ks = 0; ks < 4; ks++){
            uint32_t ca = ks*32 + aKh;
            uint32_t cb = ks*32 + bKh;
            uint32_t ah[2][4];
            #pragma unroll
            for(int mi = 0; mi < 2; mi++)
                LDSM4(ah[mi], aB + aRow[mi] + (ca ^ aXor[mi]));
            // gather 2 px of next tap (LDG latency hidden behind the MMAs below)
            if(k < 8){
                gather_px(k+1, pg*8 + ks*2,     cur ^ 1);
                gather_px(k+1, pg*8 + ks*2 + 1, cur ^ 1);
            }
            {
                uint32_t bb[2][4];
                #pragma unroll
                for(int ni = 0; ni < 2; ni++)
                    LDSM4(bb[ni], slotB + bRow[ni] + (cb ^ bXor[ni]));
                #pragma unroll
                for(int mi = 0; mi < 2; mi++)
                    #pragma unroll
                    for(int n8 = 0; n8 < 4; n8++)
                        mma_f16(acc[mi][n8], ah[mi], bb[n8>>1][(n8&1)*2], bb[n8>>1][(n8&1)*2+1]);
            }
            {
                uint32_t bb[2][4];
                #pragma unroll
                for(int ni = 0; ni < 2; ni++)
                    LDSM4(bb[ni], slotB + 8192 + bRow[ni] + (cb ^ bXor[ni]));
                #pragma unroll
                for(int mi = 0; mi < 2; mi++)
                    #pragma unroll
                    for(int n8 = 0; n8 < 4; n8++)
                        mma_f16(acc[mi][n8], ah[mi], bb[n8>>1][(n8&1)*2], bb[n8>>1][(n8&1)*2+1]);
            }
        }
        cur ^= 1;
    }

    // epilogue: BN + ReLU + store
    #pragma unroll
    for(int mi = 0; mi < 2; mi++){
        int r0 = m0 + mi*16 + (lid >> 2);
        int r1 = r0 + 8;
        #pragma unroll
        for(int n8 = 0; n8 < 4; n8++){
            int c0 = n0 + n8*8 + (lid & 3)*2;
            float iv0 = __ldg(bn + c0),      iv1 = __ldg(bn + c0 + 1);
            float bc0 = __ldg(bn + 64 + c0), bc1 = __ldg(bn + 64 + c0 + 1);
            float v00 = fmaxf(acc[mi][n8][0]*iv0 + bc0, 0.f);
            float v01 = fmaxf(acc[mi][n8][1]*iv1 + bc1, 0.f);
            float v10 = fmaxf(acc[mi][n8][2]*iv0 + bc0, 0.f);
            float v11 = fmaxf(acc[mi][n8][3]*iv1 + bc1, 0.f);
            if(NCHW_OUT){
                float* o0 = out + (((size_t)b*CH + c0)*HH + h)*WW;
                float* o1 = out + (((size_t)b*CH + c0+1)*HH + h)*WW;
                o0[r0] = v00; o1[r0] = v01;
                o0[r1] = v10; o1[r1] = v11;
            } else {
                float* base = out + ((size_t)(b*HH + h)*WW)*CH;
                *(float2*)(base + r0*CH + c0) = make_float2(v00, v01);
                *(float2*)(base + r1*CH + c0) = make_float2(v10, v11);
            }
        }
    }
}

// ---------------- launcher ----------------
extern "C" void kernel_launch(void* const* d_in, const int* in_sizes, int n_in,
                              void* d_out, int out_size)
{
    const float* x     = (const float*)d_in[0];
    const float* woff1 = (const float*)d_in[1];
    const float* boff1 = (const float*)d_in[2];
    const float* w1    = (const float*)d_in[3];
    const float* g1    = (const float*)d_in[4];
    const float* be1   = (const float*)d_in[5];
    const float* m1    = (const float*)d_in[6];
    const float* v1    = (const float*)d_in[7];
    const float* woff2 = (const float*)d_in[8];
    const float* boff2 = (const float*)d_in[9];
    const float* w2    = (const float*)d_in[10];
    const float* g2    = (const float*)d_in[11];
    const float* be2   = (const float*)d_in[12];
    const float* m2    = (const float*)d_in[13];
    const float* v2    = (const float*)d_in[14];
    float* out = (float*)d_out;

    float *xn, *y1, *offb, *bn;
    __nv_bfloat16 *wtb1, *wtb2, *wob1, *wob2;
    cudaGetSymbolAddress((void**)&xn,   g_xnhwc);
    cudaGetSymbolAddress((void**)&y1,   g_y1);
    cudaGetSymbolAddress((void**)&offb, g_off);
    cudaGetSymbolAddress((void**)&wtb1, g_wtb1);
    cudaGetSymbolAddress((void**)&wtb2, g_wtb2);
    cudaGetSymbolAddress((void**)&wob1, g_wob1);
    cudaGetSymbolAddress((void**)&wob2, g_wob2);
    cudaGetSymbolAddress((void**)&bn,   g_bn);

    cudaFuncSetAttribute(k_offt,       cudaFuncAttributeMaxDynamicSharedMemorySize, OT2_SMEM);
    cudaFuncSetAttribute(k_dcn<false>, cudaFuncAttributeMaxDynamicSharedMemorySize, DCN_SMEM);
    cudaFuncSetAttribute(k_dcn<true>,  cudaFuncAttributeMaxDynamicSharedMemorySize, DCN_SMEM);

    // launch order: k_dcn layer-1 is launch #4 (ncu effective skip = 3)
    k_prep<<<432, 256>>>(w1, w2, woff1, woff2, g1, be1, m1, v1, g2, be2, m2, v2);
    k_nchw2nhwc<<<BATCH*HH, 256>>>(x, xn);
    k_offt<<<BATCH*HH, 256, OT2_SMEM>>>(xn, wob1, boff1, offb);
    k_dcn<false><<<BATCH*HH, 256, DCN_SMEM>>>(xn, offb, wtb1, bn, y1);

    k_offt<<<BATCH*HH, 256, OT2_SMEM>>>(y1, wob2, boff2, offb);
    k_dcn<true><<<BATCH*HH, 256, DCN_SMEM>>>(y1, offb, wtb2, bn + 128, out);
}

// round 13
// speedup vs baseline: 1.0324x; 1.0324x over previous
#include <cuda_runtime.h>
#include <cuda_bf16.h>
#include <cuda_fp16.h>
#include <cstdint>

#define HH 128
#define WW 128
#define CH 64
#define BATCH 4
#define EPS 1e-5f

// ---------------- scratch (no mallocs allowed) ----------------
__device__ __align__(16) float g_xnhwc[BATCH*HH*WW*CH];
__device__ __align__(16) float g_y1   [BATCH*HH*WW*CH];
__device__ __align__(16) float g_off  [BATCH*HH*WW*18];   // layout [bh][18][128]
__device__ __align__(1024) __nv_bfloat16 g_wtb1[9*2*64*64];  // fp16 bits: hi/mid per tap
__device__ __align__(1024) __nv_bfloat16 g_wtb2[9*2*64*64];
__device__ __align__(1024) __nv_bfloat16 g_wob1[9*2*32*64];  // bf16 hi/mid (offconv)
__device__ __align__(1024) __nv_bfloat16 g_wob2[9*2*32*64];
__device__ __align__(16) float g_bn[256];

// ---------------- helpers ----------------
static __device__ __forceinline__ uint32_t smem_to_u32(const void* p){
    uint32_t a;
    asm("{ .reg .u64 t; cvta.to.shared.u64 t, %1; cvt.u32.u64 %0, t; }" : "=r"(a) : "l"(p));
    return a;
}
#define SWZ128(o) ((o) ^ (((o) >> 3) & 0x70))

#define LDSM4(r, a) \
    asm volatile("ldmatrix.sync.aligned.m8n8.x4.shared.b16 {%0,%1,%2,%3}, [%4];" \
        : "=r"((r)[0]), "=r"((r)[1]), "=r"((r)[2]), "=r"((r)[3]) : "r"(a))

static __device__ __forceinline__ void mma_bf16(float* d, const uint32_t* a, uint32_t b0, uint32_t b1){
    asm volatile("mma.sync.aligned.m16n8k16.row.col.f32.bf16.bf16.f32 "
        "{%0,%1,%2,%3},{%4,%5,%6,%7},{%8,%9},{%0,%1,%2,%3};"
        : "+f"(d[0]), "+f"(d[1]), "+f"(d[2]), "+f"(d[3])
        : "r"(a[0]), "r"(a[1]), "r"(a[2]), "r"(a[3]), "r"(b0), "r"(b1));
}
static __device__ __forceinline__ void mma_f16(float* d, const uint32_t* a, uint32_t b0, uint32_t b1){
    asm volatile("mma.sync.aligned.m16n8k16.row.col.f32.f16.f16.f32 "
        "{%0,%1,%2,%3},{%4,%5,%6,%7},{%8,%9},{%0,%1,%2,%3};"
        : "+f"(d[0]), "+f"(d[1]), "+f"(d[2]), "+f"(d[3])
        : "r"(a[0]), "r"(a[1]), "r"(a[2]), "r"(a[3]), "r"(b0), "r"(b1));
}

#define CP_ASYNC16(dst, src) \
    asm volatile("cp.async.cg.shared.global [%0], [%1], 16;" :: "r"(dst), "l"(src) : "memory")
#define CP_COMMIT() asm volatile("cp.async.commit_group;" ::: "memory")
#define CP_WAIT0()  asm volatile("cp.async.wait_group 0;" ::: "memory")

// ---------------- prep ----------------
__global__ void k_prep(const float* __restrict__ w1, const float* __restrict__ w2,
                       const float* __restrict__ woff1, const float* __restrict__ woff2,
                       const float* g1, const float* be1, const float* m1, const float* v1,
                       const float* g2, const float* be2, const float* m2, const float* v2)
{
    int i = blockIdx.x*blockDim.x + threadIdx.x;
    if(i < 73728){
        // main conv weights -> fp16 hi/mid per-tap SW128 tiles
        int L   = i / 36864;
        int rem = i % 36864;
        int k = rem >> 12;
        int o = (rem >> 6) & 63;
        int c = rem & 63;
        const float* w = L ? w2 : w1;
        float val = w[(o*64 + c)*9 + k];
        __half hb = __float2half_rn(val);
        float hf = __half2float(hb);
        __half mb = __float2half_rn(val - hf);
        char* dst = (char*)(L ? g_wtb2 : g_wtb1);
        int sw = SWZ128(o*128 + c*2);
        *(__half*)(dst + k*16384 +        sw) = hb;
        *(__half*)(dst + k*16384 + 8192 + sw) = mb;
    } else if(i < 110592){
        // offset conv weights (bf16 hi/mid)
        int j   = i - 73728;
        int L   = j / 18432;
        int rem = j % 18432;
        int k = rem >> 11;
        int o = (rem >> 6) & 31;
        int c = rem & 63;
        const float* w = L ? woff2 : woff1;
        float val = (o < 18) ? w[(o*64 + c)*9 + k] : 0.f;
        __nv_bfloat16 hb = __float2bfloat16(val);
        float hf = __bfloat162float(hb);
        __nv_bfloat16 mb = __float2bfloat16(val - hf);
        char* dst = (char*)(L ? g_wob2 : g_wob1);
        int sw = SWZ128(o*128 + c*2);
        *(__nv_bfloat16*)(dst + k*8192 +        sw) = hb;
        *(__nv_bfloat16*)(dst + k*8192 + 4096 + sw) = mb;
    }
    if(blockIdx.x == 0 && threadIdx.x < 64){
        int t = threadIdx.x;
        float i1 = g1[t] * rsqrtf(v1[t] + EPS);
        g_bn[t]      = i1;
        g_bn[64+t]   = be1[t] - m1[t]*i1;
        float i2 = g2[t] * rsqrtf(v2[t] + EPS);
        g_bn[128+t]  = i2;
        g_bn[192+t]  = be2[t] - m2[t]*i2;
    }
}

// ---------------- NCHW -> NHWC transpose ----------------
__global__ void k_nchw2nhwc(const float* __restrict__ x, float* __restrict__ xn){
    __shared__ float tile[64*129];
    int b = blockIdx.x >> 7;
    int h = blockIdx.x & 127;
    const float* src = x + (b*CH*HH)*WW + h*WW;
    for(int i = threadIdx.x; i < CH*WW; i += blockDim.x){
        int c = i >> 7, w = i & 127;
        tile[c*129 + w] = src[c*HH*WW + w];
    }
    __syncthreads();
    float* dst = xn + ((b*HH + h)*WW)*CH;
    for(int i = threadIdx.x; i < CH*WW; i += blockDim.x){
        int w = i >> 6, c = i & 63;
        dst[w*CH + c] = tile[c*129 + w];
    }
}

// ---------------- offset conv v2 (bf16 3-term, unchanged) ----------------
#define OT2_A_HI  0
#define OT2_A_MID 16640
#define OT2_B     33280
#define OT2_SMEM  49664

__global__ void __launch_bounds__(256,3) k_offt(
    const float* __restrict__ xn, const __nv_bfloat16* __restrict__ wob,
    const float* __restrict__ boff, float* __restrict__ off)
{
    extern __shared__ char smc[];
    const uint32_t smem_base = smem_to_u32(smc);

    const int b = blockIdx.x >> 7;
    const int h = blockIdx.x & 127;
    const int tid = threadIdx.x;
    const int wid = tid >> 5;
    const int lid = tid & 31;
    const int m0 = wid * 16;

    const uint32_t aKh = (lid >> 4) * 16;
    const int aR = m0 + (lid & 15);
    uint32_t bRow[2], bXor[2];
    #pragma unroll
    for(int ni = 0; ni < 2; ni++){
        int r = ni*16 + (lid & 7) + ((lid >> 4) << 3);
        bRow[ni] = r*128;
        bXor[ni] = (r & 7) << 4;
    }
    const uint32_t bKh = ((lid >> 3) & 1) * 16;

    float acc[3][4];
    #pragma unroll
    for(int n8 = 0; n8 < 3; n8++)
        #pragma unroll
        for(int j = 0; j < 4; j++) acc[n8][j] = 0.f;

    {
        const char* bs = (const char*)wob;
        #pragma unroll
        for(int j = 0; j < 2; j++)
            CP_ASYNC16(smem_base + OT2_B + tid*16 + j*4096, bs + tid*16 + j*4096);
        CP_COMMIT();
    }

    #pragma unroll 1
    for(int ky = 0; ky < 3; ky++){
        __syncthreads();
        const int hh = h + ky - 1;
        const bool hv = (hh >= 0) && (hh < HH);
        const float* rowp = xn + (size_t)(b*HH + hh)*WW*CH;
        #pragma unroll 1
        for(int idx = tid; idx < 2080; idx += 256){
            int rho = idx >> 4, q = idx & 15;
            int px = rho - 1;
            float4 v = make_float4(0.f,0.f,0.f,0.f);
            if(hv && px >= 0 && px < WW)
                v = __ldg((const float4*)(rowp + px*CH) + q);
            __nv_bfloat162 h0 = __float22bfloat162_rn(make_float2(v.x, v.y));
            __nv_bfloat162 h1 = __float22bfloat162_rn(make_float2(v.z, v.w));
            float2 f0 = __bfloat1622float2(h0);
            float2 f1 = __bfloat1622float2(h1);
            __nv_bfloat162 m0b = __float22bfloat162_rn(make_float2(v.x - f0.x, v.y - f0.y));
            __nv_bfloat162 m1b = __float22bfloat162_rn(make_float2(v.z - f1.x, v.w - f1.y));
            int sw = SWZ128(rho*128 + q*8);
            uint2 uh, um;
            uh.x = *(uint32_t*)&h0;  uh.y = *(uint32_t*)&h1;
            um.x = *(uint32_t*)&m0b; um.y = *(uint32_t*)&m1b;
            *(uint2*)(smc + OT2_A_HI  + sw) = uh;
            *(uint2*)(smc + OT2_A_MID + sw) = um;
        }

        #pragma unroll 1
        for(int kx = 0; kx < 3; kx++){
            int k = ky*3 + kx;
            CP_WAIT0();
            __syncthreads();
            if(k < 8){
                const char* bs = (const char*)wob + (k+1)*8192;
                uint32_t bd = smem_base + OT2_B + ((k+1)&1)*8192;
                #pragma unroll
                for(int j = 0; j < 2; j++)
                    CP_ASYNC16(bd + tid*16 + j*4096, bs + tid*16 + j*4096);
                CP_COMMIT();
            }
            const uint32_t slotB = smem_base + OT2_B + (k&1)*8192;
            const int rho = aR + 1 + kx - 1;
            const uint32_t aAddrBase = smem_base + OT2_A_HI + rho*128;
            const uint32_t aXor = (rho & 7) << 4;

            #pragma unroll
            for(int ks = 0; ks < 4; ks++){
                uint32_t ahi[4], ami[4], bhi[2][4], bmi[2][4];
                uint32_t ad = aAddrBase + ((ks*32 + aKh) ^ aXor);
                LDSM4(ahi, ad);
                LDSM4(ami, ad + (OT2_A_MID - OT2_A_HI));
                uint32_t cb = ks*32 + bKh;
                #pragma unroll
                for(int ni = 0; ni < 2; ni++){
                    uint32_t bd = slotB + bRow[ni] + (cb ^ bXor[ni]);
                    LDSM4(bhi[ni], bd);
                    LDSM4(bmi[ni], bd + 4096);
                }
                #pragma unroll
                for(int n8 = 0; n8 < 3; n8++){
                    uint32_t bh0 = bhi[n8>>1][(n8&1)*2], bh1 = bhi[n8>>1][(n8&1)*2+1];
                    uint32_t bm0 = bmi[n8>>1][(n8&1)*2], bm1 = bmi[n8>>1][(n8&1)*2+1];
                    mma_bf16(acc[n8], ahi, bh0, bh1);
                    mma_bf16(acc[n8], ahi, bm0, bm1);
                    mma_bf16(acc[n8], ami, bh0, bh1);
                }
            }
        }
    }

    const int r0 = m0 + (lid >> 2);
    const int r1 = r0 + 8;
    float* base = off + (size_t)(b*HH + h)*2304;
    #pragma unroll
    for(int n8 = 0; n8 < 3; n8++){
        int c0 = n8*8 + (lid & 3)*2;
        if(c0 < 18){
            float b0 = __ldg(boff + c0);
            float b1v = __ldg(boff + c0 + 1);
            base[c0*128 + r0]     = acc[n8][0] + b0;
            base[(c0+1)*128 + r0] = acc[n8][1] + b1v;
            base[c0*128 + r1]     = acc[n8][2] + b0;
            base[(c0+1)*128 + r1] = acc[n8][3] + b1v;
        }
    }
}

// ---------------- main DCN v11: fp16 2-pass, triple-buffered A, dbl B, 2 CTA ----------------
#define TB_W_OFF  0          /* float4 wtab[1152] = 18432 (premasked w00..w11) */
#define TB_I_OFF  18432      /* uint  itab[1152] = 4608 */
#define A_OFF     23040      /* 3 x 16384 fp16 A (triple buf) */
#define B_OFF     72192      /* 2 x (hi 8192 + mid 8192) */
#define DCN_SMEM  104960

template<bool NCHW_OUT>
__global__ void __launch_bounds__(256,2) k_dcn(
    const float* __restrict__ xn, const float* __restrict__ off,
    const __nv_bfloat16* __restrict__ wtb, const float* __restrict__ bn,
    float* __restrict__ out)
{
    extern __shared__ char smc[];
    const uint32_t smem_base = smem_to_u32(smc);

    const int b = blockIdx.x >> 7;
    const int h = blockIdx.x & 127;
    const int tid = threadIdx.x;
    const int wid = tid >> 5;
    const int lid = tid & 31;
    const float fh = (float)h;

    // prefetch B(0): 16KB via cp.async
    {
        const char* bs = (const char*)wtb;
        #pragma unroll
        for(int j = 0; j < 4; j++)
            CP_ASYNC16(smem_base + B_OFF + tid*16 + j*4096, bs + tid*16 + j*4096);
        CP_COMMIT();
    }

    // ---------- build fully-decoded gather table ----------
    {
        float4*   wtab = (float4*)(smc + TB_W_OFF);
        uint32_t* itab = (uint32_t*)(smc + TB_I_OFF);
        const float* offb2 = off + (size_t)(b*HH + h)*2304;
        #pragma unroll 1
        for(int e = tid; e < 1152; e += 256){
            int k  = e >> 7;
            int px = e & 127;
            float dy = __ldg(offb2 + (2*k)*128 + px);
            float dx = __ldg(offb2 + (2*k+1)*128 + px);
            float py  = fh + (float)(k/3 - 1) + dy;
            float pxx = (float)(px + k%3 - 1) + dx;
            float y0f = floorf(py), x0f = floorf(pxx);
            float wy1 = py - y0f,  wx1 = pxx - x0f;
            float wy0 = 1.f - wy1, wx0 = 1.f - wx1;
            bool vy0 = (y0f >= 0.f)  && (y0f <= 127.f);
            bool vy1 = (y0f >= -1.f) && (y0f <= 126.f);
            bool vx0 = (x0f >= 0.f)  && (x0f <= 127.f);
            bool vx1 = (x0f >= -1.f) && (x0f <= 126.f);
            float ay0 = vy0 ? wy0 : 0.f;
            float ay1 = vy1 ? wy1 : 0.f;
            float ax0 = vx0 ? wx0 : 0.f;
            float ax1 = vx1 ? wx1 : 0.f;
            uint32_t yi0 = (uint32_t)(int)fminf(fmaxf(y0f,      0.f),127.f);
            uint32_t yi1 = (uint32_t)(int)fminf(fmaxf(y0f + 1.f,0.f),127.f);
            uint32_t xi0 = (uint32_t)(int)fminf(fmaxf(x0f,      0.f),127.f);
            uint32_t xi1 = (uint32_t)(int)fminf(fmaxf(x0f + 1.f,0.f),127.f);
            wtab[e] = make_float4(ay0*ax0, ay0*ax1, ay1*ax0, ay1*ax1);
            itab[e] = yi0 | (yi1 << 7) | (xi0 << 14) | (xi1 << 21);
        }
    }

    const char* xq = (const char*)(xn + (size_t)b*HH*WW*CH) + (tid & 15)*16;
    const int q  = tid & 15;
    const int pg = tid >> 4;

    __syncthreads();  // table visible

    const float4*   wtab = (const float4*)(smc + TB_W_OFF);
    const uint32_t* itab = (const uint32_t*)(smc + TB_I_OFF);

    // gather one pixel of tap k into A buffer `buf` (fp16 single term)
    auto gather_px = [&](int k, int px, int buf){
        int e = k*128 + px;
        float4 wv = wtab[e];
        uint32_t ii = itab[e];
        uint32_t ry0 = (ii & 0x7fu) << 15;
        uint32_t ry1 = ((ii >> 7) & 0x7fu) << 15;
        uint32_t rx0 = ((ii >> 14) & 0x7fu) << 8;
        uint32_t rx1 = ((ii >> 21) & 0x7fu) << 8;
        float4 a  = __ldg((const float4*)(xq + ry0 + rx0));
        float4 b2 = __ldg((const float4*)(xq + ry0 + rx1));
        float4 c  = __ldg((const float4*)(xq + ry1 + rx0));
        float4 d  = __ldg((const float4*)(xq + ry1 + rx1));
        float4 r;
        r.x = wv.x*a.x + wv.y*b2.x + wv.z*c.x + wv.w*d.x;
        r.y = wv.x*a.y + wv.y*b2.y + wv.z*c.y + wv.w*d.y;
        r.z = wv.x*a.z + wv.y*b2.z + wv.z*c.z + wv.w*d.z;
        r.w = wv.x*a.w + wv.y*b2.w + wv.z*c.w + wv.w*d.w;
        __half2 h0 = __float22half2_rn(make_float2(r.x, r.y));
        __half2 h1 = __float22half2_rn(make_float2(r.z, r.w));
        int sw = SWZ128(px*128 + q*8);
        uint2 uh;
        uh.x = *(uint32_t*)&h0;  uh.y = *(uint32_t*)&h1;
        *(uint2*)(smc + A_OFF + buf*16384 + sw) = uh;
    };

    // prologue: gather A(0) -> buf 0, A(1) -> buf 1
    #pragma unroll 2
    for(int i = 0; i < 8; i++) gather_px(0, pg*8 + i, 0);
    #pragma unroll 2
    for(int i = 0; i < 8; i++) gather_px(1, pg*8 + i, 1);

    // mma mapping: warp (4 x 2) grid of 32x32 tiles
    const int m0 = (wid >> 1) * 32;
    const int n0 = (wid & 1) * 32;

    uint32_t aRow[2], aXor[2];
    #pragma unroll
    for(int mi = 0; mi < 2; mi++){
        int r = m0 + mi*16 + (lid & 15);
        aRow[mi] = r*128;
        aXor[mi] = (r & 7) << 4;
    }
    const uint32_t aKh = (lid >> 4) * 16;
    uint32_t bRow[2], bXor[2];
    #pragma unroll
    for(int ni = 0; ni < 2; ni++){
        int r = n0 + ni*16 + (lid & 7) + ((lid >> 4) << 3);
        bRow[ni] = r*128;
        bXor[ni] = (r & 7) << 4;
    }
    const uint32_t bKh = ((lid >> 3) & 1) * 16;

    float acc[2][4][4];
    #pragma unroll
    for(int mi = 0; mi < 2; mi++)
        #pragma unroll
        for(int ni = 0; ni < 4; ni++)
            #pragma unroll
            for(int j = 0; j < 4; j++) acc[mi][ni][j] = 0.f;

    #pragma unroll 1
    for(int k = 0; k < 9; k++){
        CP_WAIT0();          // B(k) landed
        __syncthreads();     // A(k) (gathered >=1 tap ago) + B(k) visible; old slots free
        if(k < 8){
            const char* bs = (const char*)wtb + (k+1)*16384;
            uint32_t bd = smem_base + B_OFF + ((k+1)&1)*16384;
            #pragma unroll
            for(int j = 0; j < 4; j++)
                CP_ASYNC16(bd + tid*16 + j*4096, bs + tid*16 + j*4096);
            CP_COMMIT();
        }
        const uint32_t aB    = smem_base + A_OFF + (k%3)*16384;
        const uint32_t slotB = smem_base + B_OFF + (k&1)*16384;
        const int gbuf = (k+2)%3;

        #pragma unroll
        for(int ks = 0; ks < 4; ks++){
            uint32_t ca = ks*32 + aKh;
            uint32_t cb = ks*32 + bKh;
            uint32_t ah[2][4], bh[2][4], bm[2][4];
            #pragma unroll
            for(int mi = 0; mi < 2; mi++)
                LDSM4(ah[mi], aB + aRow[mi] + (ca ^ aXor[mi]));
            #pragma unroll
            for(int ni = 0; ni < 2; ni++){
                uint32_t bd = slotB + bRow[ni] + (cb ^ bXor[ni]);
                LDSM4(bh[ni], bd);
                LDSM4(bm[ni], bd + 8192);
            }
            // gather 2 px of tap k+2 (a full tap of latency slack)
            if(k < 7){
                gather_px(k+2, pg*8 + ks*2,     gbuf);
                gather_px(k+2, pg*8 + ks*2 + 1, gbuf);
            }
            #pragma unroll
            for(int mi = 0; mi < 2; mi++)
                #pragma unroll
                for(int n8 = 0; n8 < 4; n8++){
                    mma_f16(acc[mi][n8], ah[mi], bh[n8>>1][(n8&1)*2], bh[n8>>1][(n8&1)*2+1]);
                    mma_f16(acc[mi][n8], ah[mi], bm[n8>>1][(n8&1)*2], bm[n8>>1][(n8&1)*2+1]);
                }
        }
    }

    // epilogue: BN + ReLU + store
    if(NCHW_OUT){
        // stage through smem (reuse A region) for coalesced NCHW stores
        __syncthreads();   // all ldsm reads of A buffers done
        float* sf = (float*)(smc + A_OFF);   // [64 ch][132 px-pad]
        #pragma unroll
        for(int mi = 0; mi < 2; mi++){
            int r0 = m0 + mi*16 + (lid >> 2);
            int r1 = r0 + 8;
            #pragma unroll
            for(int n8 = 0; n8 < 4; n8++){
                int c0 = n0 + n8*8 + (lid & 3)*2;
                float iv0 = __ldg(bn + c0),      iv1 = __ldg(bn + c0 + 1);
                float bc0 = __ldg(bn + 64 + c0), bc1 = __ldg(bn + 64 + c0 + 1);
                sf[c0*132 + r0]     = fmaxf(acc[mi][n8][0]*iv0 + bc0, 0.f);
                sf[(c0+1)*132 + r0] = fmaxf(acc[mi][n8][1]*iv1 + bc1, 0.f);
                sf[c0*132 + r1]     = fmaxf(acc[mi][n8][2]*iv0 + bc0, 0.f);
                sf[(c0+1)*132 + r1] = fmaxf(acc[mi][n8][3]*iv1 + bc1, 0.f);
            }
        }
        __syncthreads();
        #pragma unroll
        for(int j = 0; j < 8; j++){
            int o = wid*8 + j;
            float4 v = *(float4*)(sf + o*132 + lid*4);
            *(float4*)(out + (((size_t)b*CH + o)*HH + h)*WW + lid*4) = v;
        }
    } else {
        #pragma unroll
        for(int mi = 0; mi < 2; mi++){
            int r0 = m0 + mi*16 + (lid >> 2);
            int r1 = r0 + 8;
            #pragma unroll
            for(int n8 = 0; n8 < 4; n8++){
                int c0 = n0 + n8*8 + (lid & 3)*2;
                float iv0 = __ldg(bn + c0),      iv1 = __ldg(bn + c0 + 1);
                float bc0 = __ldg(bn + 64 + c0), bc1 = __ldg(bn + 64 + c0 + 1);
                float v00 = fmaxf(acc[mi][n8][0]*iv0 + bc0, 0.f);
                float v01 = fmaxf(acc[mi][n8][1]*iv1 + bc1, 0.f);
                float v10 = fmaxf(acc[mi][n8][2]*iv0 + bc0, 0.f);
                float v11 = fmaxf(acc[mi][n8][3]*iv1 + bc1, 0.f);
                float* base = out + ((size_t)(b*HH + h)*WW)*CH;
                *(float2*)(base + r0*CH + c0) = make_float2(v00, v01);
                *(float2*)(base + r1*CH + c0) = make_float2(v10, v11);
            }
        }
    }
}

// ---------------- launcher ----------------
extern "C" void kernel_launch(void* const* d_in, const int* in_sizes, int n_in,
                              void* d_out, int out_size)
{
    const float* x     = (const float*)d_in[0];
    const float* woff1 = (const float*)d_in[1];
    const float* boff1 = (const float*)d_in[2];
    const float* w1    = (const float*)d_in[3];
    const float* g1    = (const float*)d_in[4];
    const float* be1   = (const float*)d_in[5];
    const float* m1    = (const float*)d_in[6];
    const float* v1    = (const float*)d_in[7];
    const float* woff2 = (const float*)d_in[8];
    const float* boff2 = (const float*)d_in[9];
    const float* w2    = (const float*)d_in[10];
    const float* g2    = (const float*)d_in[11];
    const float* be2   = (const float*)d_in[12];
    const float* m2    = (const float*)d_in[13];
    const float* v2    = (const float*)d_in[14];
    float* out = (float*)d_out;

    float *xn, *y1, *offb, *bn;
    __nv_bfloat16 *wtb1, *wtb2, *wob1, *wob2;
    cudaGetSymbolAddress((void**)&xn,   g_xnhwc);
    cudaGetSymbolAddress((void**)&y1,   g_y1);
    cudaGetSymbolAddress((void**)&offb, g_off);
    cudaGetSymbolAddress((void**)&wtb1, g_wtb1);
    cudaGetSymbolAddress((void**)&wtb2, g_wtb2);
    cudaGetSymbolAddress((void**)&wob1, g_wob1);
    cudaGetSymbolAddress((void**)&wob2, g_wob2);
    cudaGetSymbolAddress((void**)&bn,   g_bn);

    cudaFuncSetAttribute(k_offt,       cudaFuncAttributeMaxDynamicSharedMemorySize, OT2_SMEM);
    cudaFuncSetAttribute(k_dcn<false>, cudaFuncAttributeMaxDynamicSharedMemorySize, DCN_SMEM);
    cudaFuncSetAttribute(k_dcn<true>,  cudaFuncAttributeMaxDynamicSharedMemorySize, DCN_SMEM);

    // launch order: k_dcn layer-1 is launch #4 (ncu effective skip = 3)
    k_prep<<<432, 256>>>(w1, w2, woff1, woff2, g1, be1, m1, v1, g2, be2, m2, v2);
    k_nchw2nhwc<<<BATCH*HH, 256>>>(x, xn);
    k_offt<<<BATCH*HH, 256, OT2_SMEM>>>(xn, wob1, boff1, offb);
    k_dcn<false><<<BATCH*HH, 256, DCN_SMEM>>>(xn, offb, wtb1, bn, y1);

    k_offt<<<BATCH*HH, 256, OT2_SMEM>>>(y1, wob2, boff2, offb);
    k_dcn<true><<<BATCH*HH, 256, DCN_SMEM>>>(y1, offb, wtb2, bn + 128, out);
}

// round 14
// speedup vs baseline: 1.0729x; 1.0392x over previous
#include <cuda_runtime.h>
#include <cuda_bf16.h>
#include <cuda_fp16.h>
#include <cstdint>

#define HH 128
#define WW 128
#define CH 64
#define BATCH 4
#define EPS 1e-5f

// ---------------- scratch (no mallocs allowed) ----------------
__device__ __align__(16) float g_xnhwc[BATCH*HH*WW*CH];
__device__ __align__(16) float g_y1   [BATCH*HH*WW*CH];
__device__ __align__(1024) __nv_bfloat16 g_wtb1[9*2*64*64];  // fp16 bits: hi/mid per tap
__device__ __align__(1024) __nv_bfloat16 g_wtb2[9*2*64*64];
__device__ __align__(1024) __nv_bfloat16 g_wob1[9*2*32*64];  // bf16 hi/mid (offconv)
__device__ __align__(1024) __nv_bfloat16 g_wob2[9*2*32*64];
__device__ __align__(16) float g_bn[256];

// ---------------- helpers ----------------
static __device__ __forceinline__ uint32_t smem_to_u32(const void* p){
    uint32_t a;
    asm("{ .reg .u64 t; cvta.to.shared.u64 t, %1; cvt.u32.u64 %0, t; }" : "=r"(a) : "l"(p));
    return a;
}
#define SWZ128(o) ((o) ^ (((o) >> 3) & 0x70))

#define LDSM4(r, a) \
    asm volatile("ldmatrix.sync.aligned.m8n8.x4.shared.b16 {%0,%1,%2,%3}, [%4];" \
        : "=r"((r)[0]), "=r"((r)[1]), "=r"((r)[2]), "=r"((r)[3]) : "r"(a))

static __device__ __forceinline__ void mma_bf16(float* d, const uint32_t* a, uint32_t b0, uint32_t b1){
    asm volatile("mma.sync.aligned.m16n8k16.row.col.f32.bf16.bf16.f32 "
        "{%0,%1,%2,%3},{%4,%5,%6,%7},{%8,%9},{%0,%1,%2,%3};"
        : "+f"(d[0]), "+f"(d[1]), "+f"(d[2]), "+f"(d[3])
        : "r"(a[0]), "r"(a[1]), "r"(a[2]), "r"(a[3]), "r"(b0), "r"(b1));
}
static __device__ __forceinline__ void mma_f16(float* d, const uint32_t* a, uint32_t b0, uint32_t b1){
    asm volatile("mma.sync.aligned.m16n8k16.row.col.f32.f16.f16.f32 "
        "{%0,%1,%2,%3},{%4,%5,%6,%7},{%8,%9},{%0,%1,%2,%3};"
        : "+f"(d[0]), "+f"(d[1]), "+f"(d[2]), "+f"(d[3])
        : "r"(a[0]), "r"(a[1]), "r"(a[2]), "r"(a[3]), "r"(b0), "r"(b1));
}

#define CP_ASYNC16(dst, src) \
    asm volatile("cp.async.cg.shared.global [%0], [%1], 16;" :: "r"(dst), "l"(src) : "memory")
#define CP_COMMIT() asm volatile("cp.async.commit_group;" ::: "memory")
#define CP_WAIT0()  asm volatile("cp.async.wait_group 0;" ::: "memory")

// ---------------- prep ----------------
__global__ void k_prep(const float* __restrict__ w1, const float* __restrict__ w2,
                       const float* __restrict__ woff1, const float* __restrict__ woff2,
                       const float* g1, const float* be1, const float* m1, const float* v1,
                       const float* g2, const float* be2, const float* m2, const float* v2)
{
    int i = blockIdx.x*blockDim.x + threadIdx.x;
    if(i < 73728){
        // main conv weights -> fp16 hi/mid per-tap SW128 tiles
        int L   = i / 36864;
        int rem = i % 36864;
        int k = rem >> 12;
        int o = (rem >> 6) & 63;
        int c = rem & 63;
        const float* w = L ? w2 : w1;
        float val = w[(o*64 + c)*9 + k];
        __half hb = __float2half_rn(val);
        float hf = __half2float(hb);
        __half mb = __float2half_rn(val - hf);
        char* dst = (char*)(L ? g_wtb2 : g_wtb1);
        int sw = SWZ128(o*128 + c*2);
        *(__half*)(dst + k*16384 +        sw) = hb;
        *(__half*)(dst + k*16384 + 8192 + sw) = mb;
    } else if(i < 110592){
        // offset conv weights (bf16 hi/mid)
        int j   = i - 73728;
        int L   = j / 18432;
        int rem = j % 18432;
        int k = rem >> 11;
        int o = (rem >> 6) & 31;
        int c = rem & 63;
        const float* w = L ? woff2 : woff1;
        float val = (o < 18) ? w[(o*64 + c)*9 + k] : 0.f;
        __nv_bfloat16 hb = __float2bfloat16(val);
        float hf = __bfloat162float(hb);
        __nv_bfloat16 mb = __float2bfloat16(val - hf);
        char* dst = (char*)(L ? g_wob2 : g_wob1);
        int sw = SWZ128(o*128 + c*2);
        *(__nv_bfloat16*)(dst + k*8192 +        sw) = hb;
        *(__nv_bfloat16*)(dst + k*8192 + 4096 + sw) = mb;
    }
    if(blockIdx.x == 0 && threadIdx.x < 64){
        int t = threadIdx.x;
        float i1 = g1[t] * rsqrtf(v1[t] + EPS);
        g_bn[t]      = i1;
        g_bn[64+t]   = be1[t] - m1[t]*i1;
        float i2 = g2[t] * rsqrtf(v2[t] + EPS);
        g_bn[128+t]  = i2;
        g_bn[192+t]  = be2[t] - m2[t]*i2;
    }
}

// ---------------- NCHW -> NHWC transpose ----------------
__global__ void k_nchw2nhwc(const float* __restrict__ x, float* __restrict__ xn){
    __shared__ float tile[64*129];
    int b = blockIdx.x >> 7;
    int h = blockIdx.x & 127;
    const float* src = x + (b*CH*HH)*WW + h*WW;
    for(int i = threadIdx.x; i < CH*WW; i += blockDim.x){
        int c = i >> 7, w = i & 127;
        tile[c*129 + w] = src[c*HH*WW + w];
    }
    __syncthreads();
    float* dst = xn + ((b*HH + h)*WW)*CH;
    for(int i = threadIdx.x; i < CH*WW; i += blockDim.x){
        int w = i >> 6, c = i & 63;
        dst[w*CH + c] = tile[c*129 + w];
    }
}

// ---------------- fused offconv + DCN kernel ----------------
// smem layout (bytes):
//   [0, 9216)            off_s : float[18][128]  (offconv results, persists into table build)
//   union region U = 9216:
//     offconv phase:  OA_HI = U         (16640)
//                     OA_MID = U+16640  (16640)
//                     OB    = U+33280   (2 x 8192)
//     dcn phase:      TW    = U         (18432)  float4 wtab[1152]
//                     TI    = U+18432   (4608)   uint itab[1152]
//                     A     = U+23040   (2 x 16384 fp16, dbl buf)
//                     B     = U+55808   (2 x 16384: hi+mid per slot)
#define F_OFFS    0
#define F_U       9216
#define F_OA_HI   (F_U)
#define F_OA_MID  (F_U + 16640)
#define F_OB      (F_U + 33280)
#define F_TW      (F_U)
#define F_TI      (F_U + 18432)
#define F_A       (F_U + 23040)
#define F_B       (F_U + 55808)
#define F_SMEM    (F_U + 88576)   /* 97792 */

template<bool NCHW_OUT>
__global__ void __launch_bounds__(256,2) k_fused(
    const float* __restrict__ xn,
    const __nv_bfloat16* __restrict__ wob, const float* __restrict__ boff,
    const __nv_bfloat16* __restrict__ wtb, const float* __restrict__ bn,
    float* __restrict__ out)
{
    extern __shared__ char smc[];
    const uint32_t smem_base = smem_to_u32(smc);

    const int b = blockIdx.x >> 7;
    const int h = blockIdx.x & 127;
    const int tid = threadIdx.x;
    const int wid = tid >> 5;
    const int lid = tid & 31;
    const float fh = (float)h;

    float* off_s = (float*)(smc + F_OFFS);

    // ================= PHASE A: offset conv (bf16 3-term) =================
    {
        const int m0o = wid * 16;
        const uint32_t aKh = (lid >> 4) * 16;
        const int aR = m0o + (lid & 15);
        uint32_t bRow[2], bXor[2];
        #pragma unroll
        for(int ni = 0; ni < 2; ni++){
            int r = ni*16 + (lid & 7) + ((lid >> 4) << 3);
            bRow[ni] = r*128;
            bXor[ni] = (r & 7) << 4;
        }
        const uint32_t bKh = ((lid >> 3) & 1) * 16;

        float acc[3][4];
        #pragma unroll
        for(int n8 = 0; n8 < 3; n8++)
            #pragma unroll
            for(int j = 0; j < 4; j++) acc[n8][j] = 0.f;

        {
            const char* bs = (const char*)wob;
            #pragma unroll
            for(int j = 0; j < 2; j++)
                CP_ASYNC16(smem_base + F_OB + tid*16 + j*4096, bs + tid*16 + j*4096);
            CP_COMMIT();
        }

        #pragma unroll 1
        for(int ky = 0; ky < 3; ky++){
            __syncthreads();
            const int hh = h + ky - 1;
            const bool hv = (hh >= 0) && (hh < HH);
            const float* rowp = xn + (size_t)(b*HH + hh)*WW*CH;
            #pragma unroll 1
            for(int idx = tid; idx < 2080; idx += 256){
                int rho = idx >> 4, q = idx & 15;
                int px = rho - 1;
                float4 v = make_float4(0.f,0.f,0.f,0.f);
                if(hv && px >= 0 && px < WW)
                    v = __ldg((const float4*)(rowp + px*CH) + q);
                __nv_bfloat162 h0 = __float22bfloat162_rn(make_float2(v.x, v.y));
                __nv_bfloat162 h1 = __float22bfloat162_rn(make_float2(v.z, v.w));
                float2 f0 = __bfloat1622float2(h0);
                float2 f1 = __bfloat1622float2(h1);
                __nv_bfloat162 m0b = __float22bfloat162_rn(make_float2(v.x - f0.x, v.y - f0.y));
                __nv_bfloat162 m1b = __float22bfloat162_rn(make_float2(v.z - f1.x, v.w - f1.y));
                int sw = SWZ128(rho*128 + q*8);
                uint2 uh, um;
                uh.x = *(uint32_t*)&h0;  uh.y = *(uint32_t*)&h1;
                um.x = *(uint32_t*)&m0b; um.y = *(uint32_t*)&m1b;
                *(uint2*)(smc + F_OA_HI  + sw) = uh;
                *(uint2*)(smc + F_OA_MID + sw) = um;
            }

            #pragma unroll 1
            for(int kx = 0; kx < 3; kx++){
                int k = ky*3 + kx;
                CP_WAIT0();
                __syncthreads();
                if(k < 8){
                    const char* bs = (const char*)wob + (k+1)*8192;
                    uint32_t bd = smem_base + F_OB + ((k+1)&1)*8192;
                    #pragma unroll
                    for(int j = 0; j < 2; j++)
                        CP_ASYNC16(bd + tid*16 + j*4096, bs + tid*16 + j*4096);
                    CP_COMMIT();
                }
                const uint32_t slotB = smem_base + F_OB + (k&1)*8192;
                const int rho = aR + kx;   // aR + 1 + kx - 1
                const uint32_t aAddrBase = smem_base + F_OA_HI + rho*128;
                const uint32_t aXor = (rho & 7) << 4;

                #pragma unroll
                for(int ks = 0; ks < 4; ks++){
                    uint32_t ahi[4], ami[4], bhi[2][4], bmi[2][4];
                    uint32_t ad = aAddrBase + ((ks*32 + aKh) ^ aXor);
                    LDSM4(ahi, ad);
                    LDSM4(ami, ad + (F_OA_MID - F_OA_HI));
                    uint32_t cb = ks*32 + bKh;
                    #pragma unroll
                    for(int ni = 0; ni < 2; ni++){
                        uint32_t bd = slotB + bRow[ni] + (cb ^ bXor[ni]);
                        LDSM4(bhi[ni], bd);
                        LDSM4(bmi[ni], bd + 4096);
                    }
                    #pragma unroll
                    for(int n8 = 0; n8 < 3; n8++){
                        uint32_t bh0 = bhi[n8>>1][(n8&1)*2], bh1 = bhi[n8>>1][(n8&1)*2+1];
                        uint32_t bm0 = bmi[n8>>1][(n8&1)*2], bm1 = bmi[n8>>1][(n8&1)*2+1];
                        mma_bf16(acc[n8], ahi, bh0, bh1);
                        mma_bf16(acc[n8], ahi, bm0, bm1);
                        mma_bf16(acc[n8], ami, bh0, bh1);
                    }
                }
            }
        }

        // epilogue -> off_s[c][px]
        const int r0 = m0o + (lid >> 2);
        const int r1 = r0 + 8;
        #pragma unroll
        for(int n8 = 0; n8 < 3; n8++){
            int c0 = n8*8 + (lid & 3)*2;
            if(c0 < 18){
                float b0 = __ldg(boff + c0);
                float b1v = __ldg(boff + c0 + 1);
                off_s[c0*128 + r0]     = acc[n8][0] + b0;
                off_s[(c0+1)*128 + r0] = acc[n8][1] + b1v;
                off_s[c0*128 + r1]     = acc[n8][2] + b0;
                off_s[(c0+1)*128 + r1] = acc[n8][3] + b1v;
            }
        }
    }
    __syncthreads();   // off_s complete; offconv tile regions free

    // ================= PHASE B: deformable conv (fp16 2-pass) =================
    // prefetch dcn B(0)
    {
        const char* bs = (const char*)wtb;
        #pragma unroll
        for(int j = 0; j < 4; j++)
            CP_ASYNC16(smem_base + F_B + tid*16 + j*4096, bs + tid*16 + j*4096);
        CP_COMMIT();
    }

    // build fully-decoded gather table from off_s
    {
        float4*   wtab = (float4*)(smc + F_TW);
        uint32_t* itab = (uint32_t*)(smc + F_TI);
        #pragma unroll 1
        for(int e = tid; e < 1152; e += 256){
            int k  = e >> 7;
            int px = e & 127;
            float dy = off_s[(2*k)*128 + px];
            float dx = off_s[(2*k+1)*128 + px];
            float py  = fh + (float)(k/3 - 1) + dy;
            float pxx = (float)(px + k%3 - 1) + dx;
            float y0f = floorf(py), x0f = floorf(pxx);
            float wy1 = py - y0f,  wx1 = pxx - x0f;
            float wy0 = 1.f - wy1, wx0 = 1.f - wx1;
            bool vy0 = (y0f >= 0.f)  && (y0f <= 127.f);
            bool vy1 = (y0f >= -1.f) && (y0f <= 126.f);
            bool vx0 = (x0f >= 0.f)  && (x0f <= 127.f);
            bool vx1 = (x0f >= -1.f) && (x0f <= 126.f);
            float ay0 = vy0 ? wy0 : 0.f;
            float ay1 = vy1 ? wy1 : 0.f;
            float ax0 = vx0 ? wx0 : 0.f;
            float ax1 = vx1 ? wx1 : 0.f;
            uint32_t yi0 = (uint32_t)(int)fminf(fmaxf(y0f,      0.f),127.f);
            uint32_t yi1 = (uint32_t)(int)fminf(fmaxf(y0f + 1.f,0.f),127.f);
            uint32_t xi0 = (uint32_t)(int)fminf(fmaxf(x0f,      0.f),127.f);
            uint32_t xi1 = (uint32_t)(int)fminf(fmaxf(x0f + 1.f,0.f),127.f);
            wtab[e] = make_float4(ay0*ax0, ay0*ax1, ay1*ax0, ay1*ax1);
            itab[e] = yi0 | (yi1 << 7) | (xi0 << 14) | (xi1 << 21);
        }
    }

    const char* xq = (const char*)(xn + (size_t)b*HH*WW*CH) + (tid & 15)*16;
    const int q  = tid & 15;
    const int pg = tid >> 4;

    __syncthreads();  // table visible

    const float4*   wtab = (const float4*)(smc + F_TW);
    const uint32_t* itab = (const uint32_t*)(smc + F_TI);

    auto gather_px = [&](int k, int px, int buf){
        int e = k*128 + px;
        float4 wv = wtab[e];
        uint32_t ii = itab[e];
        uint32_t ry0 = (ii & 0x7fu) << 15;
        uint32_t ry1 = ((ii >> 7) & 0x7fu) << 15;
        uint32_t rx0 = ((ii >> 14) & 0x7fu) << 8;
        uint32_t rx1 = ((ii >> 21) & 0x7fu) << 8;
        float4 a  = __ldg((const float4*)(xq + ry0 + rx0));
        float4 b2 = __ldg((const float4*)(xq + ry0 + rx1));
        float4 c  = __ldg((const float4*)(xq + ry1 + rx0));
        float4 d  = __ldg((const float4*)(xq + ry1 + rx1));
        float4 r;
        r.x = wv.x*a.x + wv.y*b2.x + wv.z*c.x + wv.w*d.x;
        r.y = wv.x*a.y + wv.y*b2.y + wv.z*c.y + wv.w*d.y;
        r.z = wv.x*a.z + wv.y*b2.z + wv.z*c.z + wv.w*d.z;
        r.w = wv.x*a.w + wv.y*b2.w + wv.z*c.w + wv.w*d.w;
        __half2 h0 = __float22half2_rn(make_float2(r.x, r.y));
        __half2 h1 = __float22half2_rn(make_float2(r.z, r.w));
        int sw = SWZ128(px*128 + q*8);
        uint2 uh;
        uh.x = *(uint32_t*)&h0;  uh.y = *(uint32_t*)&h1;
        *(uint2*)(smc + F_A + buf*16384 + sw) = uh;
    };

    // prologue: gather A(0) into buf 0
    #pragma unroll 2
    for(int i = 0; i < 8; i++) gather_px(0, pg*8 + i, 0);

    // mma mapping: warp (4 x 2) grid of 32x32 tiles
    const int m0 = (wid >> 1) * 32;
    const int n0 = (wid & 1) * 32;

    uint32_t aRow[2], aXor[2];
    #pragma unroll
    for(int mi = 0; mi < 2; mi++){
        int r = m0 + mi*16 + (lid & 15);
        aRow[mi] = r*128;
        aXor[mi] = (r & 7) << 4;
    }
    const uint32_t aKh = (lid >> 4) * 16;
    uint32_t bRow[2], bXor[2];
    #pragma unroll
    for(int ni = 0; ni < 2; ni++){
        int r = n0 + ni*16 + (lid & 7) + ((lid >> 4) << 3);
        bRow[ni] = r*128;
        bXor[ni] = (r & 7) << 4;
    }
    const uint32_t bKh = ((lid >> 3) & 1) * 16;

    float acc[2][4][4];
    #pragma unroll
    for(int mi = 0; mi < 2; mi++)
        #pragma unroll
        for(int ni = 0; ni < 4; ni++)
            #pragma unroll
            for(int j = 0; j < 4; j++) acc[mi][ni][j] = 0.f;

    int cur = 0;
    #pragma unroll 1
    for(int k = 0; k < 9; k++){
        CP_WAIT0();          // B(k) landed
        __syncthreads();     // A(k) + B(k) visible; old slots free
        if(k < 8){
            const char* bs = (const char*)wtb + (k+1)*16384;
            uint32_t bd = smem_base + F_B + ((k+1)&1)*16384;
            #pragma unroll
            for(int j = 0; j < 4; j++)
                CP_ASYNC16(bd + tid*16 + j*4096, bs + tid*16 + j*4096);
            CP_COMMIT();
        }
        const uint32_t aB    = smem_base + F_A + cur*16384;
        const uint32_t slotB = smem_base + F_B + (k&1)*16384;

        #pragma unroll
        for(int ks = 0; ks < 4; ks++){
            uint32_t ca = ks*32 + aKh;
            uint32_t cb = ks*32 + bKh;
            uint32_t ah[2][4], bh[2][4], bm[2][4];
            #pragma unroll
            for(int mi = 0; mi < 2; mi++)
                LDSM4(ah[mi], aB + aRow[mi] + (ca ^ aXor[mi]));
            #pragma unroll
            for(int ni = 0; ni < 2; ni++){
                uint32_t bd = slotB + bRow[ni] + (cb ^ bXor[ni]);
                LDSM4(bh[ni], bd);
                LDSM4(bm[ni], bd + 8192);
            }
            // gather 2 px of next tap (LDG latency hidden behind the MMAs below)
            if(k < 8){
                gather_px(k+1, pg*8 + ks*2,     cur ^ 1);
                gather_px(k+1, pg*8 + ks*2 + 1, cur ^ 1);
            }
            #pragma unroll
            for(int mi = 0; mi < 2; mi++)
                #pragma unroll
                for(int n8 = 0; n8 < 4; n8++){
                    mma_f16(acc[mi][n8], ah[mi], bh[n8>>1][(n8&1)*2], bh[n8>>1][(n8&1)*2+1]);
                    mma_f16(acc[mi][n8], ah[mi], bm[n8>>1][(n8&1)*2], bm[n8>>1][(n8&1)*2+1]);
                }
        }
        cur ^= 1;
    }

    // epilogue: BN + ReLU + store
    if(NCHW_OUT){
        __syncthreads();   // all ldsm reads of A/B done
        float* sf = (float*)(smc + F_A);   // [64 ch][132 px-pad] = 33792B (A+B region)
        #pragma unroll
        for(int mi = 0; mi < 2; mi++){
            int r0 = m0 + mi*16 + (lid >> 2);
            int r1 = r0 + 8;
            #pragma unroll
            for(int n8 = 0; n8 < 4; n8++){
                int c0 = n0 + n8*8 + (lid & 3)*2;
                float iv0 = __ldg(bn + c0),      iv1 = __ldg(bn + c0 + 1);
                float bc0 = __ldg(bn + 64 + c0), bc1 = __ldg(bn + 64 + c0 + 1);
                sf[c0*132 + r0]     = fmaxf(acc[mi][n8][0]*iv0 + bc0, 0.f);
                sf[(c0+1)*132 + r0] = fmaxf(acc[mi][n8][1]*iv1 + bc1, 0.f);
                sf[c0*132 + r1]     = fmaxf(acc[mi][n8][2]*iv0 + bc0, 0.f);
                sf[(c0+1)*132 + r1] = fmaxf(acc[mi][n8][3]*iv1 + bc1, 0.f);
            }
        }
        __syncthreads();
        #pragma unroll
        for(int j = 0; j < 8; j++){
            int o = wid*8 + j;
            float4 v = *(float4*)(sf + o*132 + lid*4);
            *(float4*)(out + (((size_t)b*CH + o)*HH + h)*WW + lid*4) = v;
        }
    } else {
        #pragma unroll
        for(int mi = 0; mi < 2; mi++){
            int r0 = m0 + mi*16 + (lid >> 2);
            int r1 = r0 + 8;
            #pragma unroll
            for(int n8 = 0; n8 < 4; n8++){
                int c0 = n0 + n8*8 + (lid & 3)*2;
                float iv0 = __ldg(bn + c0),      iv1 = __ldg(bn + c0 + 1);
                float bc0 = __ldg(bn + 64 + c0), bc1 = __ldg(bn + 64 + c0 + 1);
                float v00 = fmaxf(acc[mi][n8][0]*iv0 + bc0, 0.f);
                float v01 = fmaxf(acc[mi][n8][1]*iv1 + bc1, 0.f);
                float v10 = fmaxf(acc[mi][n8][2]*iv0 + bc0, 0.f);
                float v11 = fmaxf(acc[mi][n8][3]*iv1 + bc1, 0.f);
                float* base = out + ((size_t)(b*HH + h)*WW)*CH;
                *(float2*)(base + r0*CH + c0) = make_float2(v00, v01);
                *(float2*)(base + r1*CH + c0) = make_float2(v10, v11);
            }
        }
    }
}

// ---------------- launcher ----------------
extern "C" void kernel_launch(void* const* d_in, const int* in_sizes, int n_in,
                              void* d_out, int out_size)
{
    const float* x     = (const float*)d_in[0];
    const float* woff1 = (const float*)d_in[1];
    const float* boff1 = (const float*)d_in[2];
    const float* w1    = (const float*)d_in[3];
    const float* g1    = (const float*)d_in[4];
    const float* be1   = (const float*)d_in[5];
    const float* m1    = (const float*)d_in[6];
    const float* v1    = (const float*)d_in[7];
    const float* woff2 = (const float*)d_in[8];
    const float* boff2 = (const float*)d_in[9];
    const float* w2    = (const float*)d_in[10];
    const float* g2    = (const float*)d_in[11];
    const float* be2   = (const float*)d_in[12];
    const float* m2    = (const float*)d_in[13];
    const float* v2    = (const float*)d_in[14];
    float* out = (float*)d_out;

    float *xn, *y1, *bn;
    __nv_bfloat16 *wtb1, *wtb2, *wob1, *wob2;
    cudaGetSymbolAddress((void**)&xn,   g_xnhwc);
    cudaGetSymbolAddress((void**)&y1,   g_y1);
    cudaGetSymbolAddress((void**)&wtb1, g_wtb1);
    cudaGetSymbolAddress((void**)&wtb2, g_wtb2);
    cudaGetSymbolAddress((void**)&wob1, g_wob1);
    cudaGetSymbolAddress((void**)&wob2, g_wob2);
    cudaGetSymbolAddress((void**)&bn,   g_bn);

    cudaFuncSetAttribute(k_fused<false>, cudaFuncAttributeMaxDynamicSharedMemorySize, F_SMEM);
    cudaFuncSetAttribute(k_fused<true>,  cudaFuncAttributeMaxDynamicSharedMemorySize, F_SMEM);

    k_prep<<<432, 256>>>(w1, w2, woff1, woff2, g1, be1, m1, v1, g2, be2, m2, v2);
    k_nchw2nhwc<<<BATCH*HH, 256>>>(x, xn);
    k_fused<false><<<BATCH*HH, 256, F_SMEM>>>(xn, wob1, boff1, wtb1, bn, y1);
    k_fused<true><<<BATCH*HH, 256, F_SMEM>>>(y1, wob2, boff2, wtb2, bn + 128, out);
}

// round 15
// speedup vs baseline: 1.0975x; 1.0229x over previous
#include <cuda_runtime.h>
#include <cuda_bf16.h>
#include <cuda_fp16.h>
#include <cstdint>

#define HH 128
#define WW 128
#define CH 64
#define BATCH 4
#define EPS 1e-5f

// ---------------- scratch (no mallocs allowed) ----------------
__device__ __align__(16) float g_xnhwc[BATCH*HH*WW*CH];
__device__ __align__(16) float g_y1   [BATCH*HH*WW*CH];
__device__ __align__(1024) __nv_bfloat16 g_wtb1[9*2*64*64];  // fp16 bits: hi/mid per tap
__device__ __align__(1024) __nv_bfloat16 g_wtb2[9*2*64*64];
__device__ __align__(1024) __nv_bfloat16 g_wob1[9*2*32*64];  // bf16 hi/mid (offconv)
__device__ __align__(1024) __nv_bfloat16 g_wob2[9*2*32*64];
__device__ __align__(16) float g_bn[256];

// ---------------- helpers ----------------
static __device__ __forceinline__ uint32_t smem_to_u32(const void* p){
    uint32_t a;
    asm("{ .reg .u64 t; cvta.to.shared.u64 t, %1; cvt.u32.u64 %0, t; }" : "=r"(a) : "l"(p));
    return a;
}
#define SWZ128(o) ((o) ^ (((o) >> 3) & 0x70))

#define LDSM4(r, a) \
    asm volatile("ldmatrix.sync.aligned.m8n8.x4.shared.b16 {%0,%1,%2,%3}, [%4];" \
        : "=r"((r)[0]), "=r"((r)[1]), "=r"((r)[2]), "=r"((r)[3]) : "r"(a))

static __device__ __forceinline__ void mma_bf16(float* d, const uint32_t* a, uint32_t b0, uint32_t b1){
    asm volatile("mma.sync.aligned.m16n8k16.row.col.f32.bf16.bf16.f32 "
        "{%0,%1,%2,%3},{%4,%5,%6,%7},{%8,%9},{%0,%1,%2,%3};"
        : "+f"(d[0]), "+f"(d[1]), "+f"(d[2]), "+f"(d[3])
        : "r"(a[0]), "r"(a[1]), "r"(a[2]), "r"(a[3]), "r"(b0), "r"(b1));
}
static __device__ __forceinline__ void mma_f16(float* d, const uint32_t* a, uint32_t b0, uint32_t b1){
    asm volatile("mma.sync.aligned.m16n8k16.row.col.f32.f16.f16.f32 "
        "{%0,%1,%2,%3},{%4,%5,%6,%7},{%8,%9},{%0,%1,%2,%3};"
        : "+f"(d[0]), "+f"(d[1]), "+f"(d[2]), "+f"(d[3])
        : "r"(a[0]), "r"(a[1]), "r"(a[2]), "r"(a[3]), "r"(b0), "r"(b1));
}

#define CP_ASYNC16(dst, src) \
    asm volatile("cp.async.cg.shared.global [%0], [%1], 16;" :: "r"(dst), "l"(src) : "memory")
#define CP_COMMIT() asm volatile("cp.async.commit_group;" ::: "memory")
#define CP_WAIT0()  asm volatile("cp.async.wait_group 0;" ::: "memory")
#define CP_WAIT1()  asm volatile("cp.async.wait_group 1;" ::: "memory")

// ---------------- merged prep + NCHW->NHWC transpose ----------------
__global__ void k_prep_tr(const float* __restrict__ x, float* __restrict__ xn,
                          const float* __restrict__ w1, const float* __restrict__ w2,
                          const float* __restrict__ woff1, const float* __restrict__ woff2,
                          const float* g1, const float* be1, const float* m1, const float* v1,
                          const float* g2, const float* be2, const float* m2, const float* v2)
{
    // ---- weight prep (flat index over first 432 blocks' range) ----
    int i = blockIdx.x*blockDim.x + threadIdx.x;
    if(i < 73728){
        int L   = i / 36864;
        int rem = i % 36864;
        int k = rem >> 12;
        int o = (rem >> 6) & 63;
        int c = rem & 63;
        const float* w = L ? w2 : w1;
        float val = w[(o*64 + c)*9 + k];
        __half hb = __float2half_rn(val);
        float hf = __half2float(hb);
        __half mb = __float2half_rn(val - hf);
        char* dst = (char*)(L ? g_wtb2 : g_wtb1);
        int sw = SWZ128(o*128 + c*2);
        *(__half*)(dst + k*16384 +        sw) = hb;
        *(__half*)(dst + k*16384 + 8192 + sw) = mb;
    } else if(i < 110592){
        int j   = i - 73728;
        int L   = j / 18432;
        int rem = j % 18432;
        int k = rem >> 11;
        int o = (rem >> 6) & 31;
        int c = rem & 63;
        const float* w = L ? woff2 : woff1;
        float val = (o < 18) ? w[(o*64 + c)*9 + k] : 0.f;
        __nv_bfloat16 hb = __float2bfloat16(val);
        float hf = __bfloat162float(hb);
        __nv_bfloat16 mb = __float2bfloat16(val - hf);
        char* dst = (char*)(L ? g_wob2 : g_wob1);
        int sw = SWZ128(o*128 + c*2);
        *(__nv_bfloat16*)(dst + k*8192 +        sw) = hb;
        *(__nv_bfloat16*)(dst + k*8192 + 4096 + sw) = mb;
    }
    if(blockIdx.x == 0 && threadIdx.x < 64){
        int t = threadIdx.x;
        float i1 = g1[t] * rsqrtf(v1[t] + EPS);
        g_bn[t]      = i1;
        g_bn[64+t]   = be1[t] - m1[t]*i1;
        float i2 = g2[t] * rsqrtf(v2[t] + EPS);
        g_bn[128+t]  = i2;
        g_bn[192+t]  = be2[t] - m2[t]*i2;
    }

    // ---- transpose (all 512 blocks) ----
    __shared__ float tile[64*129];
    int b = blockIdx.x >> 7;
    int h = blockIdx.x & 127;
    const float* src = x + (b*CH*HH)*WW + h*WW;
    for(int e = threadIdx.x; e < CH*WW; e += blockDim.x){
        int c = e >> 7, w = e & 127;
        tile[c*129 + w] = src[c*HH*WW + w];
    }
    __syncthreads();
    float* dst = xn + ((b*HH + h)*WW)*CH;
    for(int e = threadIdx.x; e < CH*WW; e += blockDim.x){
        int w = e >> 6, c = e & 63;
        dst[w*CH + c] = tile[c*129 + w];
    }
}

// ---------------- fused offconv + DCN kernel ----------------
// smem layout (bytes):
//   [0, 9216)            off_s : float[18][128]
//   union region U = 9216:
//     offconv phase:  OA_HI = U         (16640)
//                     OA_MID = U+16640  (16640)
//                     OB    = U+33280   (2 x 24576 : per-ky tap groups)
//     dcn phase:      TW    = U         (18432)  float4 wtab[1152]
//                     TI    = U+18432   (4608)   uint itab[1152]
//                     A     = U+23040   (2 x 16384 fp16, dbl buf)
//                     B     = U+55808   (2 x 16384: hi+mid per slot)
#define F_OFFS    0
#define F_U       9216
#define F_OA_HI   (F_U)
#define F_OA_MID  (F_U + 16640)
#define F_OB      (F_U + 33280)
#define F_TW      (F_U)
#define F_TI      (F_U + 18432)
#define F_A       (F_U + 23040)
#define F_B       (F_U + 55808)
#define F_SMEM    (F_U + 88576)   /* 97792 */

template<bool NCHW_OUT>
__global__ void __launch_bounds__(256,2) k_fused(
    const float* __restrict__ xn,
    const __nv_bfloat16* __restrict__ wob, const float* __restrict__ boff,
    const __nv_bfloat16* __restrict__ wtb, const float* __restrict__ bn,
    float* __restrict__ out)
{
    extern __shared__ char smc[];
    const uint32_t smem_base = smem_to_u32(smc);

    const int b = blockIdx.x >> 7;
    const int h = blockIdx.x & 127;
    const int tid = threadIdx.x;
    const int wid = tid >> 5;
    const int lid = tid & 31;
    const float fh = (float)h;

    float* off_s = (float*)(smc + F_OFFS);

    // ================= PHASE A: offset conv (bf16 3-term, ky-grouped B) =================
    {
        const int m0o = wid * 16;
        const uint32_t aKh = (lid >> 4) * 16;
        const int aR = m0o + (lid & 15);
        uint32_t bRow[2], bXor[2];
        #pragma unroll
        for(int ni = 0; ni < 2; ni++){
            int r = ni*16 + (lid & 7) + ((lid >> 4) << 3);
            bRow[ni] = r*128;
            bXor[ni] = (r & 7) << 4;
        }
        const uint32_t bKh = ((lid >> 3) & 1) * 16;

        float acc[3][4];
        #pragma unroll
        for(int n8 = 0; n8 < 3; n8++)
            #pragma unroll
            for(int j = 0; j < 4; j++) acc[n8][j] = 0.f;

        // prologue: prefetch B group 0 (taps 0-2, 24KB)
        {
            const char* bs = (const char*)wob;
            #pragma unroll
            for(int j = 0; j < 6; j++)
                CP_ASYNC16(smem_base + F_OB + tid*16 + j*4096, bs + tid*16 + j*4096);
            CP_COMMIT();
        }

        #pragma unroll 1
        for(int ky = 0; ky < 3; ky++){
            __syncthreads();   // reads of prev tile + group(ky-1) done
            if(ky < 2){
                const char* bs = (const char*)wob + (ky+1)*24576;
                uint32_t bd = smem_base + F_OB + ((ky+1)&1)*24576;
                #pragma unroll
                for(int j = 0; j < 6; j++)
                    CP_ASYNC16(bd + tid*16 + j*4096, bs + tid*16 + j*4096);
                CP_COMMIT();
            }
            // build A tile for this ky
            const int hh = h + ky - 1;
            const bool hv = (hh >= 0) && (hh < HH);
            const float* rowp = xn + (size_t)(b*HH + hh)*WW*CH;
            #pragma unroll 1
            for(int idx = tid; idx < 2080; idx += 256){
                int rho = idx >> 4, q = idx & 15;
                int px = rho - 1;
                float4 v = make_float4(0.f,0.f,0.f,0.f);
                if(hv && px >= 0 && px < WW)
                    v = __ldg((const float4*)(rowp + px*CH) + q);
                __nv_bfloat162 h0 = __float22bfloat162_rn(make_float2(v.x, v.y));
                __nv_bfloat162 h1 = __float22bfloat162_rn(make_float2(v.z, v.w));
                float2 f0 = __bfloat1622float2(h0);
                float2 f1 = __bfloat1622float2(h1);
                __nv_bfloat162 m0b = __float22bfloat162_rn(make_float2(v.x - f0.x, v.y - f0.y));
                __nv_bfloat162 m1b = __float22bfloat162_rn(make_float2(v.z - f1.x, v.w - f1.y));
                int sw = SWZ128(rho*128 + q*8);
                uint2 uh, um;
                uh.x = *(uint32_t*)&h0;  uh.y = *(uint32_t*)&h1;
                um.x = *(uint32_t*)&m0b; um.y = *(uint32_t*)&m1b;
                *(uint2*)(smc + F_OA_HI  + sw) = uh;
                *(uint2*)(smc + F_OA_MID + sw) = um;
            }
            if(ky < 2) CP_WAIT1(); else CP_WAIT0();   // group ky landed (allow ky+1 in flight)
            __syncthreads();                           // tile + B group visible

            const uint32_t groupB = smem_base + F_OB + (ky&1)*24576;
            #pragma unroll 1
            for(int kx = 0; kx < 3; kx++){
                const uint32_t slotB = groupB + kx*8192;
                const int rho = aR + kx;
                const uint32_t aAddrBase = smem_base + F_OA_HI + rho*128;
                const uint32_t aXor = (rho & 7) << 4;

                #pragma unroll
                for(int ks = 0; ks < 4; ks++){
                    uint32_t ahi[4], ami[4], bhi[2][4], bmi[2][4];
                    uint32_t ad = aAddrBase + ((ks*32 + aKh) ^ aXor);
                    LDSM4(ahi, ad);
                    LDSM4(ami, ad + (F_OA_MID - F_OA_HI));
                    uint32_t cb = ks*32 + bKh;
                    #pragma unroll
                    for(int ni = 0; ni < 2; ni++){
                        uint32_t bd = slotB + bRow[ni] + (cb ^ bXor[ni]);
                        LDSM4(bhi[ni], bd);
                        LDSM4(bmi[ni], bd + 4096);
                    }
                    #pragma unroll
                    for(int n8 = 0; n8 < 3; n8++){
                        uint32_t bh0 = bhi[n8>>1][(n8&1)*2], bh1 = bhi[n8>>1][(n8&1)*2+1];
                        uint32_t bm0 = bmi[n8>>1][(n8&1)*2], bm1 = bmi[n8>>1][(n8&1)*2+1];
                        mma_bf16(acc[n8], ahi, bh0, bh1);
                        mma_bf16(acc[n8], ahi, bm0, bm1);
                        mma_bf16(acc[n8], ami, bh0, bh1);
                    }
                }
            }
        }

        // epilogue -> off_s[c][px]
        const int r0 = m0o + (lid >> 2);
        const int r1 = r0 + 8;
        #pragma unroll
        for(int n8 = 0; n8 < 3; n8++){
            int c0 = n8*8 + (lid & 3)*2;
            if(c0 < 18){
                float b0 = __ldg(boff + c0);
                float b1v = __ldg(boff + c0 + 1);
                off_s[c0*128 + r0]     = acc[n8][0] + b0;
                off_s[(c0+1)*128 + r0] = acc[n8][1] + b1v;
                off_s[c0*128 + r1]     = acc[n8][2] + b0;
                off_s[(c0+1)*128 + r1] = acc[n8][3] + b1v;
            }
        }
    }
    __syncthreads();   // off_s complete; offconv tile regions free

    // ================= PHASE B: deformable conv (fp16 2-pass) =================
    // prefetch dcn B(0)
    {
        const char* bs = (const char*)wtb;
        #pragma unroll
        for(int j = 0; j < 4; j++)
            CP_ASYNC16(smem_base + F_B + tid*16 + j*4096, bs + tid*16 + j*4096);
        CP_COMMIT();
    }

    // build fully-decoded gather table from off_s
    {
        float4*   wtab = (float4*)(smc + F_TW);
        uint32_t* itab = (uint32_t*)(smc + F_TI);
        #pragma unroll 1
        for(int e = tid; e < 1152; e += 256){
            int k  = e >> 7;
            int px = e & 127;
            float dy = off_s[(2*k)*128 + px];
            float dx = off_s[(2*k+1)*128 + px];
            float py  = fh + (float)(k/3 - 1) + dy;
            float pxx = (float)(px + k%3 - 1) + dx;
            float y0f = floorf(py), x0f = floorf(pxx);
            float wy1 = py - y0f,  wx1 = pxx - x0f;
            float wy0 = 1.f - wy1, wx0 = 1.f - wx1;
            bool vy0 = (y0f >= 0.f)  && (y0f <= 127.f);
            bool vy1 = (y0f >= -1.f) && (y0f <= 126.f);
            bool vx0 = (x0f >= 0.f)  && (x0f <= 127.f);
            bool vx1 = (x0f >= -1.f) && (x0f <= 126.f);
            float ay0 = vy0 ? wy0 : 0.f;
            float ay1 = vy1 ? wy1 : 0.f;
            float ax0 = vx0 ? wx0 : 0.f;
            float ax1 = vx1 ? wx1 : 0.f;
            uint32_t yi0 = (uint32_t)(int)fminf(fmaxf(y0f,      0.f),127.f);
            uint32_t yi1 = (uint32_t)(int)fminf(fmaxf(y0f + 1.f,0.f),127.f);
            uint32_t xi0 = (uint32_t)(int)fminf(fmaxf(x0f,      0.f),127.f);
            uint32_t xi1 = (uint32_t)(int)fminf(fmaxf(x0f + 1.f,0.f),127.f);
            wtab[e] = make_float4(ay0*ax0, ay0*ax1, ay1*ax0, ay1*ax1);
            itab[e] = yi0 | (yi1 << 7) | (xi0 << 14) | (xi1 << 21);
        }
    }

    const char* xq = (const char*)(xn + (size_t)b*HH*WW*CH) + (tid & 15)*16;
    const int q  = tid & 15;
    const int pg = tid >> 4;

    __syncthreads();  // table visible

    const float4*   wtab = (const float4*)(smc + F_TW);
    const uint32_t* itab = (const uint32_t*)(smc + F_TI);

    auto gather_px = [&](int k, int px, int buf){
        int e = k*128 + px;
        float4 wv = wtab[e];
        uint32_t ii = itab[e];
        uint32_t ry0 = (ii & 0x7fu) << 15;
        uint32_t ry1 = ((ii >> 7) & 0x7fu) << 15;
        uint32_t rx0 = ((ii >> 14) & 0x7fu) << 8;
        uint32_t rx1 = ((ii >> 21) & 0x7fu) << 8;
        float4 a  = __ldg((const float4*)(xq + ry0 + rx0));
        float4 b2 = __ldg((const float4*)(xq + ry0 + rx1));
        float4 c  = __ldg((const float4*)(xq + ry1 + rx0));
        float4 d  = __ldg((const float4*)(xq + ry1 + rx1));
        float4 r;
        r.x = wv.x*a.x + wv.y*b2.x + wv.z*c.x + wv.w*d.x;
        r.y = wv.x*a.y + wv.y*b2.y + wv.z*c.y + wv.w*d.y;
        r.z = wv.x*a.z + wv.y*b2.z + wv.z*c.z + wv.w*d.z;
        r.w = wv.x*a.w + wv.y*b2.w + wv.z*c.w + wv.w*d.w;
        __half2 h0 = __float22half2_rn(make_float2(r.x, r.y));
        __half2 h1 = __float22half2_rn(make_float2(r.z, r.w));
        int sw = SWZ128(px*128 + q*8);
        uint2 uh;
        uh.x = *(uint32_t*)&h0;  uh.y = *(uint32_t*)&h1;
        *(uint2*)(smc + F_A + buf*16384 + sw) = uh;
    };

    // prologue: gather A(0) into buf 0
    #pragma unroll 2
    for(int i = 0; i < 8; i++) gather_px(0, pg*8 + i, 0);

    // mma mapping: warp (4 x 2) grid of 32x32 tiles
    const int m0 = (wid >> 1) * 32;
    const int n0 = (wid & 1) * 32;

    uint32_t aRow[2], aXor[2];
    #pragma unroll
    for(int mi = 0; mi < 2; mi++){
        int r = m0 + mi*16 + (lid & 15);
        aRow[mi] = r*128;
        aXor[mi] = (r & 7) << 4;
    }
    const uint32_t aKh = (lid >> 4) * 16;
    uint32_t bRow[2], bXor[2];
    #pragma unroll
    for(int ni = 0; ni < 2; ni++){
        int r = n0 + ni*16 + (lid & 7) + ((lid >> 4) << 3);
        bRow[ni] = r*128;
        bXor[ni] = (r & 7) << 4;
    }
    const uint32_t bKh = ((lid >> 3) & 1) * 16;

    float acc[2][4][4];
    #pragma unroll
    for(int mi = 0; mi < 2; mi++)
        #pragma unroll
        for(int ni = 0; ni < 4; ni++)
            #pragma unroll
            for(int j = 0; j < 4; j++) acc[mi][ni][j] = 0.f;

    int cur = 0;
    #pragma unroll 1
    for(int k = 0; k < 9; k++){
        CP_WAIT0();          // B(k) landed
        __syncthreads();     // A(k) + B(k) visible; old slots free
        if(k < 8){
            const char* bs = (const char*)wtb + (k+1)*16384;
            uint32_t bd = smem_base + F_B + ((k+1)&1)*16384;
            #pragma unroll
            for(int j = 0; j < 4; j++)
                CP_ASYNC16(bd + tid*16 + j*4096, bs + tid*16 + j*4096);
            CP_COMMIT();
        }
        const uint32_t aB    = smem_base + F_A + cur*16384;
        const uint32_t slotB = smem_base + F_B + (k&1)*16384;

        #pragma unroll
        for(int ks = 0; ks < 4; ks++){
            uint32_t ca = ks*32 + aKh;
            uint32_t cb = ks*32 + bKh;
            uint32_t ah[2][4], bh[2][4], bm[2][4];
            #pragma unroll
            for(int mi = 0; mi < 2; mi++)
                LDSM4(ah[mi], aB + aRow[mi] + (ca ^ aXor[mi]));
            #pragma unroll
            for(int ni = 0; ni < 2; ni++){
                uint32_t bd = slotB + bRow[ni] + (cb ^ bXor[ni]);
                LDSM4(bh[ni], bd);
                LDSM4(bm[ni], bd + 8192);
            }
            // gather 2 px of next tap (LDG latency hidden behind the MMAs below)
            if(k < 8){
                gather_px(k+1, pg*8 + ks*2,     cur ^ 1);
                gather_px(k+1, pg*8 + ks*2 + 1, cur ^ 1);
            }
            #pragma unroll
            for(int mi = 0; mi < 2; mi++)
                #pragma unroll
                for(int n8 = 0; n8 < 4; n8++){
                    mma_f16(acc[mi][n8], ah[mi], bh[n8>>1][(n8&1)*2], bh[n8>>1][(n8&1)*2+1]);
                    mma_f16(acc[mi][n8], ah[mi], bm[n8>>1][(n8&1)*2], bm[n8>>1][(n8&1)*2+1]);
                }
        }
        cur ^= 1;
    }

    // epilogue: BN + ReLU + store
    if(NCHW_OUT){
        __syncthreads();   // all ldsm reads of A/B done
        float* sf = (float*)(smc + F_A);   // [64 ch][132 px-pad]
        #pragma unroll
        for(int mi = 0; mi < 2; mi++){
            int r0 = m0 + mi*16 + (lid >> 2);
            int r1 = r0 + 8;
            #pragma unroll
            for(int n8 = 0; n8 < 4; n8++){
                int c0 = n0 + n8*8 + (lid & 3)*2;
                float iv0 = __ldg(bn + c0),      iv1 = __ldg(bn + c0 + 1);
                float bc0 = __ldg(bn + 64 + c0), bc1 = __ldg(bn + 64 + c0 + 1);
                sf[c0*132 + r0]     = fmaxf(acc[mi][n8][0]*iv0 + bc0, 0.f);
                sf[(c0+1)*132 + r0] = fmaxf(acc[mi][n8][1]*iv1 + bc1, 0.f);
                sf[c0*132 + r1]     = fmaxf(acc[mi][n8][2]*iv0 + bc0, 0.f);
                sf[(c0+1)*132 + r1] = fmaxf(acc[mi][n8][3]*iv1 + bc1, 0.f);
            }
        }
        __syncthreads();
        #pragma unroll
        for(int j = 0; j < 8; j++){
            int o = wid*8 + j;
            float4 v = *(float4*)(sf + o*132 + lid*4);
            *(float4*)(out + (((size_t)b*CH + o)*HH + h)*WW + lid*4) = v;
        }
    } else {
        #pragma unroll
        for(int mi = 0; mi < 2; mi++){
            int r0 = m0 + mi*16 + (lid >> 2);
            int r1 = r0 + 8;
            #pragma unroll
            for(int n8 = 0; n8 < 4; n8++){
                int c0 = n0 + n8*8 + (lid & 3)*2;
                float iv0 = __ldg(bn + c0),      iv1 = __ldg(bn + c0 + 1);
                float bc0 = __ldg(bn + 64 + c0), bc1 = __ldg(bn + 64 + c0 + 1);
                float v00 = fmaxf(acc[mi][n8][0]*iv0 + bc0, 0.f);
                float v01 = fmaxf(acc[mi][n8][1]*iv1 + bc1, 0.f);
                float v10 = fmaxf(acc[mi][n8][2]*iv0 + bc0, 0.f);
                float v11 = fmaxf(acc[mi][n8][3]*iv1 + bc1, 0.f);
                float* base = out + ((size_t)(b*HH + h)*WW)*CH;
                *(float2*)(base + r0*CH + c0) = make_float2(v00, v01);
                *(float2*)(base + r1*CH + c0) = make_float2(v10, v11);
            }
        }
    }
}

// ---------------- launcher ----------------
extern "C" void kernel_launch(void* const* d_in, const int* in_sizes, int n_in,
                              void* d_out, int out_size)
{
    const float* x     = (const float*)d_in[0];
    const float* woff1 = (const float*)d_in[1];
    const float* boff1 = (const float*)d_in[2];
    const float* w1    = (const float*)d_in[3];
    const float* g1    = (const float*)d_in[4];
    const float* be1   = (const float*)d_in[5];
    const float* m1    = (const float*)d_in[6];
    const float* v1    = (const float*)d_in[7];
    const float* woff2 = (const float*)d_in[8];
    const float* boff2 = (const float*)d_in[9];
    const float* w2    = (const float*)d_in[10];
    const float* g2    = (const float*)d_in[11];
    const float* be2   = (const float*)d_in[12];
    const float* m2    = (const float*)d_in[13];
    const float* v2    = (const float*)d_in[14];
    float* out = (float*)d_out;

    float *xn, *y1, *bn;
    __nv_bfloat16 *wtb1, *wtb2, *wob1, *wob2;
    cudaGetSymbolAddress((void**)&xn,   g_xnhwc);
    cudaGetSymbolAddress((void**)&y1,   g_y1);
    cudaGetSymbolAddress((void**)&wtb1, g_wtb1);
    cudaGetSymbolAddress((void**)&wtb2, g_wtb2);
    cudaGetSymbolAddress((void**)&wob1, g_wob1);
    cudaGetSymbolAddress((void**)&wob2, g_wob2);
    cudaGetSymbolAddress((void**)&bn,   g_bn);

    cudaFuncSetAttribute(k_fused<false>, cudaFuncAttributeMaxDynamicSharedMemorySize, F_SMEM);
    cudaFuncSetAttribute(k_fused<true>,  cudaFuncAttributeMaxDynamicSharedMemorySize, F_SMEM);

    k_prep_tr<<<BATCH*HH, 256>>>(x, xn, w1, w2, woff1, woff2,
                                 g1, be1, m1, v1, g2, be2, m2, v2);
    k_fused<false><<<BATCH*HH, 256, F_SMEM>>>(xn, wob1, boff1, wtb1, bn, y1);
    k_fused<true><<<BATCH*HH, 256, F_SMEM>>>(y1, wob2, boff2, wtb2, bn + 128, out);
}

// round 16
// speedup vs baseline: 1.0978x; 1.0003x over previous
#include <cuda_runtime.h>
#include <cuda_bf16.h>
#include <cuda_fp16.h>
#include <cstdint>

#define HH 128
#define WW 128
#define CH 64
#define BATCH 4
#define EPS 1e-5f

// ---------------- scratch (no mallocs allowed) ----------------
__device__ __align__(16) float g_xnhwc[BATCH*HH*WW*CH];
__device__ __align__(16) float g_y1   [BATCH*HH*WW*CH];
__device__ __align__(1024) __nv_bfloat16 g_wtb1[9*2*64*64];  // fp16 bits: hi/mid per tap
__device__ __align__(1024) __nv_bfloat16 g_wtb2[9*2*64*64];
__device__ __align__(1024) __nv_bfloat16 g_wob1[9*2*32*64];  // bf16 hi/mid (offconv)
__device__ __align__(1024) __nv_bfloat16 g_wob2[9*2*32*64];
__device__ __align__(16) float g_bn[256];

// ---------------- helpers ----------------
static __device__ __forceinline__ uint32_t smem_to_u32(const void* p){
    uint32_t a;
    asm("{ .reg .u64 t; cvta.to.shared.u64 t, %1; cvt.u32.u64 %0, t; }" : "=r"(a) : "l"(p));
    return a;
}
#define SWZ128(o) ((o) ^ (((o) >> 3) & 0x70))

#define LDSM4(r, a) \
    asm volatile("ldmatrix.sync.aligned.m8n8.x4.shared.b16 {%0,%1,%2,%3}, [%4];" \
        : "=r"((r)[0]), "=r"((r)[1]), "=r"((r)[2]), "=r"((r)[3]) : "r"(a))

static __device__ __forceinline__ void mma_bf16(float* d, const uint32_t* a, uint32_t b0, uint32_t b1){
    asm volatile("mma.sync.aligned.m16n8k16.row.col.f32.bf16.bf16.f32 "
        "{%0,%1,%2,%3},{%4,%5,%6,%7},{%8,%9},{%0,%1,%2,%3};"
        : "+f"(d[0]), "+f"(d[1]), "+f"(d[2]), "+f"(d[3])
        : "r"(a[0]), "r"(a[1]), "r"(a[2]), "r"(a[3]), "r"(b0), "r"(b1));
}
static __device__ __forceinline__ void mma_f16(float* d, const uint32_t* a, uint32_t b0, uint32_t b1){
    asm volatile("mma.sync.aligned.m16n8k16.row.col.f32.f16.f16.f32 "
        "{%0,%1,%2,%3},{%4,%5,%6,%7},{%8,%9},{%0,%1,%2,%3};"
        : "+f"(d[0]), "+f"(d[1]), "+f"(d[2]), "+f"(d[3])
        : "r"(a[0]), "r"(a[1]), "r"(a[2]), "r"(a[3]), "r"(b0), "r"(b1));
}

#define CP_ASYNC16(dst, src) \
    asm volatile("cp.async.cg.shared.global [%0], [%1], 16;" :: "r"(dst), "l"(src) : "memory")
#define CP_COMMIT() asm volatile("cp.async.commit_group;" ::: "memory")
#define CP_WAIT0()  asm volatile("cp.async.wait_group 0;" ::: "memory")
#define CP_WAIT1()  asm volatile("cp.async.wait_group 1;" ::: "memory")

// ---------------- merged prep + NCHW->NHWC transpose (vectorized) ----------------
__global__ void k_prep_tr(const float* __restrict__ x, float* __restrict__ xn,
                          const float* __restrict__ w1, const float* __restrict__ w2,
                          const float* __restrict__ woff1, const float* __restrict__ woff2,
                          const float* g1, const float* be1, const float* m1, const float* v1,
                          const float* g2, const float* be2, const float* m2, const float* v2)
{
    // ---- weight prep (flat index over first 432 blocks' range) ----
    int i = blockIdx.x*blockDim.x + threadIdx.x;
    if(i < 73728){
        int L   = i / 36864;
        int rem = i % 36864;
        int k = rem >> 12;
        int o = (rem >> 6) & 63;
        int c = rem & 63;
        const float* w = L ? w2 : w1;
        float val = w[(o*64 + c)*9 + k];
        __half hb = __float2half_rn(val);
        float hf = __half2float(hb);
        __half mb = __float2half_rn(val - hf);
        char* dst = (char*)(L ? g_wtb2 : g_wtb1);
        int sw = SWZ128(o*128 + c*2);
        *(__half*)(dst + k*16384 +        sw) = hb;
        *(__half*)(dst + k*16384 + 8192 + sw) = mb;
    } else if(i < 110592){
        int j   = i - 73728;
        int L   = j / 18432;
        int rem = j % 18432;
        int k = rem >> 11;
        int o = (rem >> 6) & 31;
        int c = rem & 63;
        const float* w = L ? woff2 : woff1;
        float val = (o < 18) ? w[(o*64 + c)*9 + k] : 0.f;
        __nv_bfloat16 hb = __float2bfloat16(val);
        float hf = __bfloat162float(hb);
        __nv_bfloat16 mb = __float2bfloat16(val - hf);
        char* dst = (char*)(L ? g_wob2 : g_wob1);
        int sw = SWZ128(o*128 + c*2);
        *(__nv_bfloat16*)(dst + k*8192 +        sw) = hb;
        *(__nv_bfloat16*)(dst + k*8192 + 4096 + sw) = mb;
    }
    if(blockIdx.x == 0 && threadIdx.x < 64){
        int t = threadIdx.x;
        float i1 = g1[t] * rsqrtf(v1[t] + EPS);
        g_bn[t]      = i1;
        g_bn[64+t]   = be1[t] - m1[t]*i1;
        float i2 = g2[t] * rsqrtf(v2[t] + EPS);
        g_bn[128+t]  = i2;
        g_bn[192+t]  = be2[t] - m2[t]*i2;
    }

    // ---- transpose (all 512 blocks), float4 both gmem sides ----
    __shared__ float tile[64*129];
    int b = blockIdx.x >> 7;
    int h = blockIdx.x & 127;
    const float* src = x + (size_t)(b*CH*HH + 0)*WW + h*WW;
    #pragma unroll
    for(int e = threadIdx.x; e < 2048; e += 256){
        int c = e >> 5, w4 = e & 31;
        float4 v = *(const float4*)(src + (size_t)c*HH*WW + w4*4);
        tile[c*129 + 4*w4 + 0] = v.x;
        tile[c*129 + 4*w4 + 1] = v.y;
        tile[c*129 + 4*w4 + 2] = v.z;
        tile[c*129 + 4*w4 + 3] = v.w;
    }
    __syncthreads();
    float* dst = xn + ((size_t)(b*HH + h)*WW)*CH;
    #pragma unroll
    for(int e = threadIdx.x; e < 2048; e += 256){
        int c4 = e & 15, w = e >> 4;
        float4 v;
        v.x = tile[(c4*4+0)*129 + w];
        v.y = tile[(c4*4+1)*129 + w];
        v.z = tile[(c4*4+2)*129 + w];
        v.w = tile[(c4*4+3)*129 + w];
        *(float4*)(dst + w*CH + c4*4) = v;
    }
}

// ---------------- fused offconv + DCN kernel ----------------
// smem layout (bytes):
//   [0, 9216)            off_s : float[18][128]
//   union region U = 9216:
//     offconv phase:  OA_HI = U         (16640)
//                     OA_MID = U+16640  (16640)
//                     OB    = U+33280   (2 x 24576 : per-ky tap groups)
//     dcn phase:      TW    = U         (18432)  float4 wtab[1152]
//                     TI    = U+18432   (4608)   uint itab[1152]
//                     A     = U+23040   (2 x 16384 fp16, dbl buf)
//                     B     = U+55808   (2 x 16384: hi+mid per slot)
#define F_OFFS    0
#define F_U       9216
#define F_OA_HI   (F_U)
#define F_OA_MID  (F_U + 16640)
#define F_OB      (F_U + 33280)
#define F_TW      (F_U)
#define F_TI      (F_U + 18432)
#define F_A       (F_U + 23040)
#define F_B       (F_U + 55808)
#define F_SMEM    (F_U + 88576)   /* 97792 */

template<bool NCHW_OUT>
__global__ void __launch_bounds__(256,2) k_fused(
    const float* __restrict__ xn,
    const __nv_bfloat16* __restrict__ wob, const float* __restrict__ boff,
    const __nv_bfloat16* __restrict__ wtb, const float* __restrict__ bn,
    float* __restrict__ out)
{
    extern __shared__ char smc[];
    const uint32_t smem_base = smem_to_u32(smc);

    const int b = blockIdx.x >> 7;
    const int h = blockIdx.x & 127;
    const int tid = threadIdx.x;
    const int wid = tid >> 5;
    const int lid = tid & 31;
    const float fh = (float)h;

    float* off_s = (float*)(smc + F_OFFS);

    // ================= PHASE A: offset conv (bf16 3-term, ky-grouped B) =================
    {
        const int m0o = wid * 16;
        const uint32_t aKh = (lid >> 4) * 16;
        const int aR = m0o + (lid & 15);
        uint32_t bRow[2], bXor[2];
        #pragma unroll
        for(int ni = 0; ni < 2; ni++){
            int r = ni*16 + (lid & 7) + ((lid >> 4) << 3);
            bRow[ni] = r*128;
            bXor[ni] = (r & 7) << 4;
        }
        const uint32_t bKh = ((lid >> 3) & 1) * 16;

        float acc[3][4];
        #pragma unroll
        for(int n8 = 0; n8 < 3; n8++)
            #pragma unroll
            for(int j = 0; j < 4; j++) acc[n8][j] = 0.f;

        // prologue: prefetch B group 0 (taps 0-2, 24KB)
        {
            const char* bs = (const char*)wob;
            #pragma unroll
            for(int j = 0; j < 6; j++)
                CP_ASYNC16(smem_base + F_OB + tid*16 + j*4096, bs + tid*16 + j*4096);
            CP_COMMIT();
        }

        #pragma unroll 1
        for(int ky = 0; ky < 3; ky++){
            __syncthreads();   // reads of prev tile + group(ky-1) done
            if(ky < 2){
                const char* bs = (const char*)wob + (ky+1)*24576;
                uint32_t bd = smem_base + F_OB + ((ky+1)&1)*24576;
                #pragma unroll
                for(int j = 0; j < 6; j++)
                    CP_ASYNC16(bd + tid*16 + j*4096, bs + tid*16 + j*4096);
                CP_COMMIT();
            }
            // build A tile for this ky
            const int hh = h + ky - 1;
            const bool hv = (hh >= 0) && (hh < HH);
            const float* rowp = xn + (size_t)(b*HH + hh)*WW*CH;
            #pragma unroll 1
            for(int idx = tid; idx < 2080; idx += 256){
                int rho = idx >> 4, q = idx & 15;
                int px = rho - 1;
                float4 v = make_float4(0.f,0.f,0.f,0.f);
                if(hv && px >= 0 && px < WW)
                    v = __ldg((const float4*)(rowp + px*CH) + q);
                __nv_bfloat162 h0 = __float22bfloat162_rn(make_float2(v.x, v.y));
                __nv_bfloat162 h1 = __float22bfloat162_rn(make_float2(v.z, v.w));
                float2 f0 = __bfloat1622float2(h0);
                float2 f1 = __bfloat1622float2(h1);
                __nv_bfloat162 m0b = __float22bfloat162_rn(make_float2(v.x - f0.x, v.y - f0.y));
                __nv_bfloat162 m1b = __float22bfloat162_rn(make_float2(v.z - f1.x, v.w - f1.y));
                int sw = SWZ128(rho*128 + q*8);
                uint2 uh, um;
                uh.x = *(uint32_t*)&h0;  uh.y = *(uint32_t*)&h1;
                um.x = *(uint32_t*)&m0b; um.y = *(uint32_t*)&m1b;
                *(uint2*)(smc + F_OA_HI  + sw) = uh;
                *(uint2*)(smc + F_OA_MID + sw) = um;
            }
            if(ky < 2) CP_WAIT1(); else CP_WAIT0();   // group ky landed (allow ky+1 in flight)
            __syncthreads();                           // tile + B group visible

            const uint32_t groupB = smem_base + F_OB + (ky&1)*24576;
            #pragma unroll 1
            for(int kx = 0; kx < 3; kx++){
                const uint32_t slotB = groupB + kx*8192;
                const int rho = aR + kx;
                const uint32_t aAddrBase = smem_base + F_OA_HI + rho*128;
                const uint32_t aXor = (rho & 7) << 4;

                #pragma unroll
                for(int ks = 0; ks < 4; ks++){
                    uint32_t ahi[4], ami[4], bhi[2][4], bmi[2][4];
                    uint32_t ad = aAddrBase + ((ks*32 + aKh) ^ aXor);
                    LDSM4(ahi, ad);
                    LDSM4(ami, ad + (F_OA_MID - F_OA_HI));
                    uint32_t cb = ks*32 + bKh;
                    #pragma unroll
                    for(int ni = 0; ni < 2; ni++){
                        uint32_t bd = slotB + bRow[ni] + (cb ^ bXor[ni]);
                        LDSM4(bhi[ni], bd);
                        LDSM4(bmi[ni], bd + 4096);
                    }
                    #pragma unroll
                    for(int n8 = 0; n8 < 3; n8++){
                        uint32_t bh0 = bhi[n8>>1][(n8&1)*2], bh1 = bhi[n8>>1][(n8&1)*2+1];
                        uint32_t bm0 = bmi[n8>>1][(n8&1)*2], bm1 = bmi[n8>>1][(n8&1)*2+1];
                        mma_bf16(acc[n8], ahi, bh0, bh1);
                        mma_bf16(acc[n8], ahi, bm0, bm1);
                        mma_bf16(acc[n8], ami, bh0, bh1);
                    }
                }
            }
        }

        // epilogue -> off_s[c][px]
        const int r0 = m0o + (lid >> 2);
        const int r1 = r0 + 8;
        #pragma unroll
        for(int n8 = 0; n8 < 3; n8++){
            int c0 = n8*8 + (lid & 3)*2;
            if(c0 < 18){
                float b0 = __ldg(boff + c0);
                float b1v = __ldg(boff + c0 + 1);
                off_s[c0*128 + r0]     = acc[n8][0] + b0;
                off_s[(c0+1)*128 + r0] = acc[n8][1] + b1v;
                off_s[c0*128 + r1]     = acc[n8][2] + b0;
                off_s[(c0+1)*128 + r1] = acc[n8][3] + b1v;
            }
        }
    }
    __syncthreads();   // off_s complete; offconv tile regions free

    // ================= PHASE B: deformable conv (fp16 2-pass) =================
    // prefetch dcn B(0)
    {
        const char* bs = (const char*)wtb;
        #pragma unroll
        for(int j = 0; j < 4; j++)
            CP_ASYNC16(smem_base + F_B + tid*16 + j*4096, bs + tid*16 + j*4096);
        CP_COMMIT();
    }

    // build fully-decoded gather table from off_s
    {
        float4*   wtab = (float4*)(smc + F_TW);
        uint32_t* itab = (uint32_t*)(smc + F_TI);
        #pragma unroll 1
        for(int e = tid; e < 1152; e += 256){
            int k  = e >> 7;
            int px = e & 127;
            float dy = off_s[(2*k)*128 + px];
            float dx = off_s[(2*k+1)*128 + px];
            float py  = fh + (float)(k/3 - 1) + dy;
            float pxx = (float)(px + k%3 - 1) + dx;
            float y0f = floorf(py), x0f = floorf(pxx);
            float wy1 = py - y0f,  wx1 = pxx - x0f;
            float wy0 = 1.f - wy1, wx0 = 1.f - wx1;
            bool vy0 = (y0f >= 0.f)  && (y0f <= 127.f);
            bool vy1 = (y0f >= -1.f) && (y0f <= 126.f);
            bool vx0 = (x0f >= 0.f)  && (x0f <= 127.f);
            bool vx1 = (x0f >= -1.f) && (x0f <= 126.f);
            float ay0 = vy0 ? wy0 : 0.f;
            float ay1 = vy1 ? wy1 : 0.f;
            float ax0 = vx0 ? wx0 : 0.f;
            float ax1 = vx1 ? wx1 : 0.f;
            uint32_t yi0 = (uint32_t)(int)fminf(fmaxf(y0f,      0.f),127.f);
            uint32_t yi1 = (uint32_t)(int)fminf(fmaxf(y0f + 1.f,0.f),127.f);
            uint32_t xi0 = (uint32_t)(int)fminf(fmaxf(x0f,      0.f),127.f);
            uint32_t xi1 = (uint32_t)(int)fminf(fmaxf(x0f + 1.f,0.f),127.f);
            wtab[e] = make_float4(ay0*ax0, ay0*ax1, ay1*ax0, ay1*ax1);
            itab[e] = yi0 | (yi1 << 7) | (xi0 << 14) | (xi1 << 21);
        }
    }

    const char* xq = (const char*)(xn + (size_t)b*HH*WW*CH) + (tid & 15)*16;
    const int q  = tid & 15;
    const int pg = tid >> 4;

    __syncthreads();  // table visible

    const float4*   wtab = (const float4*)(smc + F_TW);
    const uint32_t* itab = (const uint32_t*)(smc + F_TI);

    auto gather_px = [&](int k, int px, int buf){
        int e = k*128 + px;
        float4 wv = wtab[e];
        uint32_t ii = itab[e];
        uint32_t ry0 = (ii & 0x7fu) << 15;
        uint32_t ry1 = ((ii >> 7) & 0x7fu) << 15;
        uint32_t rx0 = ((ii >> 14) & 0x7fu) << 8;
        uint32_t rx1 = ((ii >> 21) & 0x7fu) << 8;
        float4 a  = __ldg((const float4*)(xq + ry0 + rx0));
        float4 b2 = __ldg((const float4*)(xq + ry0 + rx1));
        float4 c  = __ldg((const float4*)(xq + ry1 + rx0));
        float4 d  = __ldg((const float4*)(xq + ry1 + rx1));
        float4 r;
        r.x = wv.x*a.x + wv.y*b2.x + wv.z*c.x + wv.w*d.x;
        r.y = wv.x*a.y + wv.y*b2.y + wv.z*c.y + wv.w*d.y;
        r.z = wv.x*a.z + wv.y*b2.z + wv.z*c.z + wv.w*d.z;
        r.w = wv.x*a.w + wv.y*b2.w + wv.z*c.w + wv.w*d.w;
        __half2 h0 = __float22half2_rn(make_float2(r.x, r.y));
        __half2 h1 = __float22half2_rn(make_float2(r.z, r.w));
        int sw = SWZ128(px*128 + q*8);
        uint2 uh;
        uh.x = *(uint32_t*)&h0;  uh.y = *(uint32_t*)&h1;
        *(uint2*)(smc + F_A + buf*16384 + sw) = uh;
    };

    // prologue: gather A(0) into buf 0
    #pragma unroll 2
    for(int i = 0; i < 8; i++) gather_px(0, pg*8 + i, 0);

    // mma mapping: warp (4 x 2) grid of 32x32 tiles
    const int m0 = (wid >> 1) * 32;
    const int n0 = (wid & 1) * 32;

    uint32_t aRow[2], aXor[2];
    #pragma unroll
    for(int mi = 0; mi < 2; mi++){
        int r = m0 + mi*16 + (lid & 15);
        aRow[mi] = r*128;
        aXor[mi] = (r & 7) << 4;
    }
    const uint32_t aKh = (lid >> 4) * 16;
    uint32_t bRow[2], bXor[2];
    #pragma unroll
    for(int ni = 0; ni < 2; ni++){
        int r = n0 + ni*16 + (lid & 7) + ((lid >> 4) << 3);
        bRow[ni] = r*128;
        bXor[ni] = (r & 7) << 4;
    }
    const uint32_t bKh = ((lid >> 3) & 1) * 16;

    float acc[2][4][4];
    #pragma unroll
    for(int mi = 0; mi < 2; mi++)
        #pragma unroll
        for(int ni = 0; ni < 4; ni++)
            #pragma unroll
            for(int j = 0; j < 4; j++) acc[mi][ni][j] = 0.f;

    int cur = 0;
    #pragma unroll 1
    for(int k = 0; k < 9; k++){
        CP_WAIT0();          // B(k) landed
        __syncthreads();     // A(k) + B(k) visible; old slots free
        if(k < 8){
            const char* bs = (const char*)wtb + (k+1)*16384;
            uint32_t bd = smem_base + F_B + ((k+1)&1)*16384;
            #pragma unroll
            for(int j = 0; j < 4; j++)
                CP_ASYNC16(bd + tid*16 + j*4096, bs + tid*16 + j*4096);
            CP_COMMIT();
        }
        const uint32_t aB    = smem_base + F_A + cur*16384;
        const uint32_t slotB = smem_base + F_B + (k&1)*16384;

        #pragma unroll
        for(int ks = 0; ks < 4; ks++){
            uint32_t ca = ks*32 + aKh;
            uint32_t cb = ks*32 + bKh;
            // issue next-tap gather LDGs FIRST (max latency cover before the
            // asm-volatile ldsm/mma block pins the schedule)
            if(k < 8){
                gather_px(k+1, pg*8 + ks*2,     cur ^ 1);
                gather_px(k+1, pg*8 + ks*2 + 1, cur ^ 1);
            }
            uint32_t ah[2][4], bh[2][4], bm[2][4];
            #pragma unroll
            for(int mi = 0; mi < 2; mi++)
                LDSM4(ah[mi], aB + aRow[mi] + (ca ^ aXor[mi]));
            #pragma unroll
            for(int ni = 0; ni < 2; ni++){
                uint32_t bd = slotB + bRow[ni] + (cb ^ bXor[ni]);
                LDSM4(bh[ni], bd);
                LDSM4(bm[ni], bd + 8192);
            }
            #pragma unroll
            for(int mi = 0; mi < 2; mi++)
                #pragma unroll
                for(int n8 = 0; n8 < 4; n8++){
                    mma_f16(acc[mi][n8], ah[mi], bh[n8>>1][(n8&1)*2], bh[n8>>1][(n8&1)*2+1]);
                    mma_f16(acc[mi][n8], ah[mi], bm[n8>>1][(n8&1)*2], bm[n8>>1][(n8&1)*2+1]);
                }
        }
        cur ^= 1;
    }

    // epilogue: BN + ReLU + store
    if(NCHW_OUT){
        __syncthreads();   // all ldsm reads of A/B done
        float* sf = (float*)(smc + F_A);   // [64 ch][132 px-pad]
        #pragma unroll
        for(int mi = 0; mi < 2; mi++){
            int r0 = m0 + mi*16 + (lid >> 2);
            int r1 = r0 + 8;
            #pragma unroll
            for(int n8 = 0; n8 < 4; n8++){
                int c0 = n0 + n8*8 + (lid & 3)*2;
                float iv0 = __ldg(bn + c0),      iv1 = __ldg(bn + c0 + 1);
                float bc0 = __ldg(bn + 64 + c0), bc1 = __ldg(bn + 64 + c0 + 1);
                sf[c0*132 + r0]     = fmaxf(acc[mi][n8][0]*iv0 + bc0, 0.f);
                sf[(c0+1)*132 + r0] = fmaxf(acc[mi][n8][1]*iv1 + bc1, 0.f);
                sf[c0*132 + r1]     = fmaxf(acc[mi][n8][2]*iv0 + bc0, 0.f);
                sf[(c0+1)*132 + r1] = fmaxf(acc[mi][n8][3]*iv1 + bc1, 0.f);
            }
        }
        __syncthreads();
        #pragma unroll
        for(int j = 0; j < 8; j++){
            int o = wid*8 + j;
            float4 v = *(float4*)(sf + o*132 + lid*4);
            *(float4*)(out + (((size_t)b*CH + o)*HH + h)*WW + lid*4) = v;
        }
    } else {
        #pragma unroll
        for(int mi = 0; mi < 2; mi++){
            int r0 = m0 + mi*16 + (lid >> 2);
            int r1 = r0 + 8;
            #pragma unroll
            for(int n8 = 0; n8 < 4; n8++){
                int c0 = n0 + n8*8 + (lid & 3)*2;
                float iv0 = __ldg(bn + c0),      iv1 = __ldg(bn + c0 + 1);
                float bc0 = __ldg(bn + 64 + c0), bc1 = __ldg(bn + 64 + c0 + 1);
                float v00 = fmaxf(acc[mi][n8][0]*iv0 + bc0, 0.f);
                float v01 = fmaxf(acc[mi][n8][1]*iv1 + bc1, 0.f);
                float v10 = fmaxf(acc[mi][n8][2]*iv0 + bc0, 0.f);
                float v11 = fmaxf(acc[mi][n8][3]*iv1 + bc1, 0.f);
                float* base = out + ((size_t)(b*HH + h)*WW)*CH;
                *(float2*)(base + r0*CH + c0) = make_float2(v00, v01);
                *(float2*)(base + r1*CH + c0) = make_float2(v10, v11);
            }
        }
    }
}

// ---------------- launcher ----------------
extern "C" void kernel_launch(void* const* d_in, const int* in_sizes, int n_in,
                              void* d_out, int out_size)
{
    const float* x     = (const float*)d_in[0];
    const float* woff1 = (const float*)d_in[1];
    const float* boff1 = (const float*)d_in[2];
    const float* w1    = (const float*)d_in[3];
    const float* g1    = (const float*)d_in[4];
    const float* be1   = (const float*)d_in[5];
    const float* m1    = (const float*)d_in[6];
    const float* v1    = (const float*)d_in[7];
    const float* woff2 = (const float*)d_in[8];
    const float* boff2 = (const float*)d_in[9];
    const float* w2    = (const float*)d_in[10];
    const float* g2    = (const float*)d_in[11];
    const float* be2   = (const float*)d_in[12];
    const float* m2    = (const float*)d_in[13];
    const float* v2    = (const float*)d_in[14];
    float* out = (float*)d_out;

    float *xn, *y1, *bn;
    __nv_bfloat16 *wtb1, *wtb2, *wob1, *wob2;
    cudaGetSymbolAddress((void**)&xn,   g_xnhwc);
    cudaGetSymbolAddress((void**)&y1,   g_y1);
    cudaGetSymbolAddress((void**)&wtb1, g_wtb1);
    cudaGetSymbolAddress((void**)&wtb2, g_wtb2);
    cudaGetSymbolAddress((void**)&wob1, g_wob1);
    cudaGetSymbolAddress((void**)&wob2, g_wob2);
    cudaGetSymbolAddress((void**)&bn,   g_bn);

    cudaFuncSetAttribute(k_fused<false>, cudaFuncAttributeMaxDynamicSharedMemorySize, F_SMEM);
    cudaFuncSetAttribute(k_fused<true>,  cudaFuncAttributeMaxDynamicSharedMemorySize, F_SMEM);

    k_prep_tr<<<BATCH*HH, 256>>>(x, xn, w1, w2, woff1, woff2,
                                 g1, be1, m1, v1, g2, be2, m2, v2);
    k_fused<false><<<BATCH*HH, 256, F_SMEM>>>(xn, wob1, boff1, wtb1, bn, y1);
    k_fused<true><<<BATCH*HH, 256, F_SMEM>>>(y1, wob2, boff2, wtb2, bn + 128, out);
}